// round 9
// baseline (speedup 1.0000x reference)
#include <cuda_runtime.h>
#include <cuda_bf16.h>
#include <cuda_fp16.h>
#include <cstdint>
#include <math.h>

#define SEQ 2048
#define HID 2048
#define HD  128
#define NH  16
#define NKV 4
#define KVW (NKV*HD)           // 512
#define NQKV (HID + 2*KVW)     // 3072
#define EPSV 1e-6f
#define BKG 64
#define NSTG 4
#define KCH (HID / BKG)        // 32 k-chunks
#define GP  72                 // gemm smem row stride (halves)

// ---------------- scratch ----------------------------------------------------
__device__ float g_Y[SEQ * HID];

__device__ __half g_Ah[SEQ * HID];               // hidden split hi
__device__ __half g_Al[SEQ * HID];               // hidden split lo
__device__ __half g_AOh[SEQ * HID];              // attention-out split hi
__device__ __half g_AOl[SEQ * HID];
__device__ __half g_Wqkv[NQKV * HID];            // W^T fp16
__device__ __half g_Wo[HID * HID];

__device__ __half g_Qf[SEQ * HID];               // Q fp16 (post norm/rope)
__device__ __half g_Kf[SEQ * KVW];               // K fp16
__device__ __half g_Vf[SEQ * KVW];               // V fp16

// ======================= helpers =============================================
__device__ __forceinline__ uint32_t smem_u32(const void* p) {
    uint32_t a;
    asm("{ .reg .u64 t; cvta.to.shared.u64 t, %1; cvt.u32.u64 %0, t; }" : "=r"(a) : "l"(p));
    return a;
}
__device__ __forceinline__ void ldsm4(uint32_t* r, uint32_t addr) {
    asm volatile("ldmatrix.sync.aligned.m8n8.x4.shared.b16 {%0,%1,%2,%3}, [%4];"
        : "=r"(r[0]), "=r"(r[1]), "=r"(r[2]), "=r"(r[3]) : "r"(addr));
}
__device__ __forceinline__ void ldsm4t(uint32_t* r, uint32_t addr) {
    asm volatile("ldmatrix.sync.aligned.m8n8.x4.trans.shared.b16 {%0,%1,%2,%3}, [%4];"
        : "=r"(r[0]), "=r"(r[1]), "=r"(r[2]), "=r"(r[3]) : "r"(addr));
}
__device__ __forceinline__ void mma_f16(float* c, const uint32_t* a, const uint32_t* b) {
    asm volatile(
        "mma.sync.aligned.m16n8k16.row.col.f32.f16.f16.f32 "
        "{%0,%1,%2,%3}, {%4,%5,%6,%7}, {%8,%9}, {%0,%1,%2,%3};"
        : "+f"(c[0]), "+f"(c[1]), "+f"(c[2]), "+f"(c[3])
        : "r"(a[0]), "r"(a[1]), "r"(a[2]), "r"(a[3]), "r"(b[0]), "r"(b[1]));
}
__device__ __forceinline__ void cpa16(void* s, const void* g) {
    uint32_t sa = smem_u32(s);
    asm volatile("cp.async.cg.shared.global [%0], [%1], 16;" :: "r"(sa), "l"(g));
}

// ===== fp16 2-term GEMM core: C = (Ah+Al) @ B^T, 4-stage cp.async ===========
#define STAGE_HALF (3 * 128 * GP)
#define GEMM_SMEM  (NSTG * STAGE_HALF * 2)

struct GemmAcc { float a[4][4][4]; };

__device__ __forceinline__ void gemm_core(const __half* __restrict__ Ah,
                                          const __half* __restrict__ Al,
                                          const __half* __restrict__ B,
                                          int bm, int bn, __half* gs, GemmAcc& G)
{
    const int tid  = threadIdx.x;
    const int wid  = tid >> 5, lane = tid & 31;
    const int wm   = wid & 1, wn = wid >> 1;
    const uint32_t sbase = smem_u32(gs);

#define ISSUE(c) do {                                                                   \
    int _k0 = (c) * BKG;                                                                \
    __half* _sA = gs + ((c) % NSTG) * STAGE_HALF;                                       \
    __half* _sL = _sA + 128 * GP;                                                       \
    __half* _sB = _sL + 128 * GP;                                                       \
    _Pragma("unroll")                                                                   \
    for (int _i = 0; _i < 4; _i++) {                                                    \
        int _id = _i * 256 + tid; int _r = _id >> 3, _u = _id & 7;                      \
        int _so = _r * GP + _u * 8;                                                     \
        size_t _ga = (size_t)(bm + _r) * HID + _k0 + _u * 8;                            \
        cpa16(_sA + _so, Ah + _ga);                                                     \
        cpa16(_sL + _so, Al + _ga);                                                     \
        cpa16(_sB + _so, B + (size_t)(bn + _r) * HID + _k0 + _u * 8);                   \
    }                                                                                   \
    asm volatile("cp.async.commit_group;" ::: "memory");                                \
} while (0)

#pragma unroll
    for (int i = 0; i < 4; i++)
#pragma unroll
        for (int j = 0; j < 4; j++)
#pragma unroll
            for (int k = 0; k < 4; k++) G.a[i][j][k] = 0.0f;

    ISSUE(0); ISSUE(1); ISSUE(2);

    const uint32_t aOff = (uint32_t)((wm * 64 + (lane & 15)) * GP + ((lane >> 4) << 3)) * 2;
    const uint32_t bOff = (uint32_t)((wn * 32 + (lane & 7) + (((lane >> 4) & 1) << 3)) * GP
                                     + (((lane >> 3) & 1) << 3)) * 2;

    for (int c = 0; c < KCH; c++) {
        asm volatile("cp.async.wait_group 2;" ::: "memory");
        __syncthreads();
        if (c + 3 < KCH) { ISSUE(c + 3); }
        else { asm volatile("cp.async.commit_group;" ::: "memory"); }

        const uint32_t aB = sbase + (c % NSTG) * (STAGE_HALF * 2);
        const uint32_t lB = aB + 128 * GP * 2;
        const uint32_t bB = lB + 128 * GP * 2;
#pragma unroll
        for (int ks = 0; ks < 4; ks++) {
            uint32_t ah[4][4], al[4][4], bfr[2][4];
#pragma unroll
            for (int mi = 0; mi < 4; mi++) {
                ldsm4(ah[mi], aB + aOff + mi * (16 * GP * 2) + ks * 32);
                ldsm4(al[mi], lB + aOff + mi * (16 * GP * 2) + ks * 32);
            }
#pragma unroll
            for (int nj = 0; nj < 2; nj++)
                ldsm4(bfr[nj], bB + bOff + nj * (16 * GP * 2) + ks * 32);
#pragma unroll
            for (int mi = 0; mi < 4; mi++)
#pragma unroll
                for (int ni = 0; ni < 4; ni++) {
                    mma_f16(G.a[mi][ni], ah[mi], &bfr[ni >> 1][(ni & 1) * 2]);
                    mma_f16(G.a[mi][ni], al[mi], &bfr[ni >> 1][(ni & 1) * 2]);
                }
        }
    }
#undef ISSUE
}

// ---- fused QKV projection + per-head RMSNorm + RoPE + fp16 outputs ----------
__global__ __launch_bounds__(256) void gemm_qkv(const float* __restrict__ cosT,
                                                const float* __restrict__ sinT,
                                                const float* __restrict__ qscale,
                                                const float* __restrict__ kscale)
{
    extern __shared__ char dynsm[];
    GemmAcc G;
    const int bm = blockIdx.y * 128, bn = blockIdx.x * 128;
    gemm_core(g_Ah, g_Al, g_Wqkv, bm, bn, (__half*)dynsm, G);

    const int tid = threadIdx.x;
    const int lane = tid & 31, wid = tid >> 5;
    const int wm = wid & 1, wn = wid >> 1;

    asm volatile("cp.async.wait_group 0;" ::: "memory");
    __syncthreads();

    // ---- V tiles: plain fp16 store ----
    if (bn >= HID + KVW) {
        const int head = (bn - HID - KVW) >> 7;
#pragma unroll
        for (int mi = 0; mi < 4; mi++)
#pragma unroll
            for (int half = 0; half < 2; half++) {
                int s = bm + wm * 64 + mi * 16 + (lane >> 2) + half * 8;
#pragma unroll
                for (int ni = 0; ni < 4; ni++) {
                    int d = wn * 32 + (lane & 3) * 2 + ni * 8;
                    __half2 v = __floats2half2_rn(G.a[mi][ni][half * 2],
                                                  G.a[mi][ni][half * 2 + 1]);
                    *(__half2*)(g_Vf + (size_t)s * KVW + head * HD + d) = v;
                }
            }
        return;
    }

    // ---- Q / K tiles: RMSNorm + RoPE ----
    const bool isQ = (bn < HID);
    const int head = isQ ? (bn >> 7) : ((bn - HID) >> 7);
    const float* sc = isQ ? qscale : kscale;

    float* red = (float*)dynsm;
    float* stg = (float*)dynsm + 512 + 16;
#define STG(r, d) stg[(r) * 132 + (d)]

    float scv[4][2];
#pragma unroll
    for (int ni = 0; ni < 4; ni++) {
#pragma unroll
        for (int e2 = 0; e2 < 2; e2++)
            scv[ni][e2] = sc[wn * 32 + (lane & 3) * 2 + ni * 8 + e2];
    }

#pragma unroll
    for (int mi = 0; mi < 4; mi++) {
#pragma unroll
        for (int half = 0; half < 2; half++) {
            float p = 0.0f;
#pragma unroll
            for (int ni = 0; ni < 4; ni++) {
                float v0 = G.a[mi][ni][half * 2], v1 = G.a[mi][ni][half * 2 + 1];
                p += v0 * v0 + v1 * v1;
            }
            p += __shfl_xor_sync(0xffffffffu, p, 1);
            p += __shfl_xor_sync(0xffffffffu, p, 2);
            if ((lane & 3) == 0) {
                int r = wm * 64 + mi * 16 + (lane >> 2) + half * 8;
                red[r * 4 + wn] = p;
            }
        }
    }
    __syncthreads();

#pragma unroll
    for (int mi = 0; mi < 4; mi++) {
#pragma unroll
        for (int half = 0; half < 2; half++) {
            int r = wm * 64 + mi * 16 + (lane >> 2) + half * 8;
            float tot = red[r * 4] + red[r * 4 + 1] + red[r * 4 + 2] + red[r * 4 + 3];
            float inv = rsqrtf(tot * (1.0f / HD) + EPSV);
#pragma unroll
            for (int ni = 0; ni < 4; ni++) {
#pragma unroll
                for (int e2 = 0; e2 < 2; e2++) {
                    int d = wn * 32 + (lane & 3) * 2 + ni * 8 + e2;
                    float nv = G.a[mi][ni][half * 2 + e2] * inv * scv[ni][e2];
                    G.a[mi][ni][half * 2 + e2] = nv;
                    STG(r, d) = nv;
                }
            }
        }
    }
    __syncthreads();

#pragma unroll
    for (int mi = 0; mi < 4; mi++) {
#pragma unroll
        for (int half = 0; half < 2; half++) {
            int r = wm * 64 + mi * 16 + (lane >> 2) + half * 8;
            int s = bm + r;
#pragma unroll
            for (int ni = 0; ni < 4; ni++) {
                int d = wn * 32 + (lane & 3) * 2 + ni * 8;
                float nv0 = G.a[mi][ni][half * 2], nv1 = G.a[mi][ni][half * 2 + 1];
                float rot0, rot1;
                if (d < 64) { rot0 = -STG(r, d + 64); rot1 = -STG(r, d + 65); }
                else        { rot0 =  STG(r, d - 64); rot1 =  STG(r, d - 63); }
                float2 cv = *(const float2*)(cosT + (size_t)s * HD + d);
                float2 sv = *(const float2*)(sinT + (size_t)s * HD + d);
                float o0 = nv0 * cv.x + rot0 * sv.x;
                float o1 = nv1 * cv.y + rot1 * sv.y;
                __half2 hv = __floats2half2_rn(o0, o1);
                if (isQ) *(__half2*)(g_Qf + (size_t)s * HID + head * HD + d) = hv;
                else     *(__half2*)(g_Kf + (size_t)s * KVW + head * HD + d) = hv;
            }
        }
    }
#undef STG
}

// ---- Wo projection ----
__global__ __launch_bounds__(256) void gemm_wo()
{
    extern __shared__ char dynsm[];
    GemmAcc G;
    const int bm = blockIdx.y * 128, bn = blockIdx.x * 128;
    gemm_core(g_AOh, g_AOl, g_Wo, bm, bn, (__half*)dynsm, G);

    const int lane = threadIdx.x & 31, wid = threadIdx.x >> 5;
    const int cr = bm + (wid & 1) * 64 + (lane >> 2);
    const int cc = bn + (wid >> 1) * 32 + (lane & 3) * 2;
#pragma unroll
    for (int mi = 0; mi < 4; mi++)
#pragma unroll
        for (int ni = 0; ni < 4; ni++) {
            *(float2*)&g_Y[(size_t)(cr + mi * 16) * HID + cc + ni * 8] =
                make_float2(G.a[mi][ni][0], G.a[mi][ni][1]);
            *(float2*)&g_Y[(size_t)(cr + mi * 16 + 8) * HID + cc + ni * 8] =
                make_float2(G.a[mi][ni][2], G.a[mi][ni][3]);
        }
}

// =========== split-convert hidden: f32 -> Ah, Al fp16 ========================
__global__ void conv_act(const float* __restrict__ X)
{
    int idx = (blockIdx.x * blockDim.x + threadIdx.x) * 2;
    float2 x = *(const float2*)(X + idx);
    __half h0 = __float2half_rn(x.x);
    __half h1 = __float2half_rn(x.y);
    __half l0 = __float2half_rn(x.x - __half2float(h0));
    __half l1 = __float2half_rn(x.y - __half2float(h1));
    __half2 hv; hv.x = h0; hv.y = h1;
    __half2 lv; lv.x = l0; lv.y = l1;
    *(__half2*)(g_Ah + idx) = hv;
    *(__half2*)(g_Al + idx) = lv;
}

// ==== transpose all 4 weights: W[HID,N] f32 -> Wt[N,HID] fp16, one launch ====
__global__ void conv_wt_all(const float* __restrict__ Wq, const float* __restrict__ Wk,
                            const float* __restrict__ Wv, const float* __restrict__ Wo)
{
    __shared__ float t[32][33];
    const float* W; __half* Wt; int N;
    __half *wqkv = g_Wqkv, *wo = g_Wo;
    switch (blockIdx.z) {
        case 0: W = Wq; Wt = wqkv;                             N = HID; break;
        case 1: W = Wk; Wt = wqkv + (size_t)HID * HID;         N = KVW; break;
        case 2: W = Wv; Wt = wqkv + (size_t)(HID + KVW) * HID; N = KVW; break;
        default: W = Wo; Wt = wo;                              N = HID; break;
    }
    int n0 = blockIdx.x * 32, k0 = blockIdx.y * 32;
    if (n0 >= N) return;
    int tx = threadIdx.x, ty0 = threadIdx.y;
#pragma unroll
    for (int i = 0; i < 4; i++) {
        int ty = ty0 + i * 8;
        t[ty][tx] = W[(size_t)(k0 + ty) * N + n0 + tx];
    }
    __syncthreads();
#pragma unroll
    for (int i = 0; i < 4; i++) {
        int n = n0 + ty0 + i * 8;
        int k = k0 + tx;
        Wt[(size_t)n * HID + k] = __float2half_rn(t[tx][ty0 + i * 8]);
    }
}

// ---------------- causal GQA flash attention, fp16 single-term ---------------
// 256 threads = 8 warps; 128 q-rows; K/V 64-row tiles double-buffered.
// Q single fp16, P single fp16 -> half the MMAs of R8; 2 CTAs/SM target.
#define AP 136
#define KVBUF (2 * 64 * AP)
#define ATT_SMEM ((128 * AP + 2 * KVBUF) * 2)

__global__ __launch_bounds__(256, 2) void attn_mma()
{
    extern __shared__ char dynsm[];
    __half* sm = (__half*)dynsm;
    __half* Qf = sm;
    __half* KV = sm + 128 * AP;

    const int qb = 15 - blockIdx.x;
    const int h  = blockIdx.y;
    const int kv = h >> 2;
    const int tid = threadIdx.x, w = tid >> 5, l = tid & 31;
    const float scl = 0.08838834764831845f;
    const int kmax = 2 * qb + 1;

    const __half* gkf = g_Kf + kv * HD;
    const __half* gvf = g_Vf + kv * HD;

#define ISSUE_KV(kb) do {                                                              \
    __half* _d = KV + ((kb) & 1) * KVBUF;                                              \
    size_t _g0 = (size_t)((kb) * 64) * KVW;                                            \
    _Pragma("unroll")                                                                  \
    for (int _i = 0; _i < 4; _i++) {                                                   \
        int _id = _i * 256 + tid; int _r = _id >> 4, _u = _id & 15;                    \
        size_t _go = _g0 + (size_t)_r * KVW + _u * 8;                                  \
        int _so = _r * AP + _u * 8;                                                    \
        cpa16(_d + _so,           gkf + _go);                                          \
        cpa16(_d + 64 * AP + _so, gvf + _go);                                          \
    }                                                                                  \
    asm volatile("cp.async.commit_group;" ::: "memory");                               \
} while (0)

    ISSUE_KV(0);

    {
        const __half* gq = g_Qf + (size_t)(qb * 128) * HID + h * HD;
#pragma unroll
        for (int i = 0; i < 8; i++) {
            int id = i * 256 + tid;
            int r = id >> 4, u = id & 15;
            *(uint4*)(Qf + r * AP + u * 8) = *(const uint4*)(gq + (size_t)r * HID + u * 8);
        }
    }

    const uint32_t qa = smem_u32(Qf);
    const uint32_t aOff = (uint32_t)((w * 16 + (l & 15)) * AP + ((l >> 4) << 3)) * 2;

    float m0 = -1e30f, m1 = -1e30f, ls0 = 0.0f, ls1 = 0.0f;
    float accO[16][4];
#pragma unroll
    for (int i = 0; i < 16; i++)
#pragma unroll
        for (int j = 0; j < 4; j++) accO[i][j] = 0.0f;

    for (int kb = 0; kb <= kmax; kb++) {
        asm volatile("cp.async.wait_group 0;" ::: "memory");
        __syncthreads();
        if (kb < kmax) ISSUE_KV(kb + 1);

        const __half* buf = KV + (kb & 1) * KVBUF;
        const uint32_t ka = smem_u32(buf);
        const uint32_t va = ka + 64 * AP * 2;

        // ---- S = Q · K (single fp16) ----
        float S[8][4];
#pragma unroll
        for (int t = 0; t < 8; t++)
#pragma unroll
            for (int e = 0; e < 4; e++) S[t][e] = 0.0f;

#pragma unroll
        for (int ks = 0; ks < 8; ks++) {
            uint32_t af[4], bf2[4][4];
            ldsm4(af, qa + aOff + ks * 32);
#pragma unroll
            for (int g = 0; g < 4; g++)
                ldsm4(bf2[g], ka + (uint32_t)((g * 16 + (l & 7) + (((l >> 4) & 1) << 3)) * AP
                                              + (((l >> 3) & 1) << 3)) * 2 + ks * 32);
#pragma unroll
            for (int t = 0; t < 8; t++)
                mma_f16(S[t], af, &bf2[t >> 1][(t & 1) * 2]);
        }

#pragma unroll
        for (int t = 0; t < 8; t++)
#pragma unroll
            for (int e = 0; e < 4; e++) S[t][e] *= scl;

        if (kb >= 2 * qb) {
            int r0 = qb * 128 + w * 16 + (l >> 2), r1 = r0 + 8;
            int cbase = kb * 64 + (l & 3) * 2;
#pragma unroll
            for (int t = 0; t < 8; t++) {
                int cb = cbase + t * 8;
                if (cb     > r0) S[t][0] = -1e30f;
                if (cb + 1 > r0) S[t][1] = -1e30f;
                if (cb     > r1) S[t][2] = -1e30f;
                if (cb + 1 > r1) S[t][3] = -1e30f;
            }
        }

        float mx0 = -1e30f, mx1 = -1e30f;
#pragma unroll
        for (int t = 0; t < 8; t++) {
            mx0 = fmaxf(mx0, fmaxf(S[t][0], S[t][1]));
            mx1 = fmaxf(mx1, fmaxf(S[t][2], S[t][3]));
        }
        mx0 = fmaxf(mx0, __shfl_xor_sync(0xffffffffu, mx0, 1));
        mx0 = fmaxf(mx0, __shfl_xor_sync(0xffffffffu, mx0, 2));
        mx1 = fmaxf(mx1, __shfl_xor_sync(0xffffffffu, mx1, 1));
        mx1 = fmaxf(mx1, __shfl_xor_sync(0xffffffffu, mx1, 2));

        float nm0 = fmaxf(m0, mx0), nm1 = fmaxf(m1, mx1);
        float cr0 = __expf(m0 - nm0), cr1 = __expf(m1 - nm1);
        m0 = nm0; m1 = nm1;
        ls0 *= cr0; ls1 *= cr1;
#pragma unroll
        for (int t = 0; t < 16; t++) {
            accO[t][0] *= cr0; accO[t][1] *= cr0;
            accO[t][2] *= cr1; accO[t][3] *= cr1;
        }

        // P = exp(S - m) -> single fp16 fragments
        uint32_t Pa[4][4];
        float rs0 = 0.0f, rs1 = 0.0f;
#pragma unroll
        for (int t = 0; t < 8; t++) {
            float p0 = __expf(S[t][0] - nm0), p1 = __expf(S[t][1] - nm0);
            float p2 = __expf(S[t][2] - nm1), p3 = __expf(S[t][3] - nm1);
            rs0 += p0 + p1; rs1 += p2 + p3;
            __half2 h01 = __floats2half2_rn(p0, p1);
            __half2 h23 = __floats2half2_rn(p2, p3);
            int kc = t >> 1, hi = (t & 1) * 2;
            Pa[kc][hi]     = *(uint32_t*)&h01;
            Pa[kc][hi + 1] = *(uint32_t*)&h23;
        }
        rs0 += __shfl_xor_sync(0xffffffffu, rs0, 1);
        rs0 += __shfl_xor_sync(0xffffffffu, rs0, 2);
        rs1 += __shfl_xor_sync(0xffffffffu, rs1, 1);
        rs1 += __shfl_xor_sync(0xffffffffu, rs1, 2);
        ls0 += rs0; ls1 += rs1;

        // ---- PV: acc += P · V ----
#pragma unroll
        for (int kc = 0; kc < 4; kc++) {
            uint32_t vb[8][4];
#pragma unroll
            for (int g = 0; g < 8; g++)
                ldsm4t(vb[g], va + (uint32_t)((kc * 16 + (l & 15)) * AP
                                              + (g * 16 + ((l >> 4) << 3))) * 2);
#pragma unroll
            for (int nd = 0; nd < 16; nd++)
                mma_f16(accO[nd], Pa[kc], &vb[nd >> 1][(nd & 1) * 2]);
        }
    }
#undef ISSUE_KV

    // epilogue: write AOh / AOl fp16 splits (Wo stays 2-term)
    float inv0 = 1.0f / ls0, inv1 = 1.0f / ls1;
    int r0 = qb * 128 + w * 16 + (l >> 2);
    int cc = h * HD + (l & 3) * 2;
#pragma unroll
    for (int nd = 0; nd < 16; nd++) {
        float v00 = accO[nd][0] * inv0, v01 = accO[nd][1] * inv0;
        float v10 = accO[nd][2] * inv1, v11 = accO[nd][3] * inv1;
        __half2 h0 = __floats2half2_rn(v00, v01);
        __half2 l0v = __floats2half2_rn(v00 - __half2float(h0.x), v01 - __half2float(h0.y));
        __half2 h1 = __floats2half2_rn(v10, v11);
        __half2 l1v = __floats2half2_rn(v10 - __half2float(h1.x), v11 - __half2float(h1.y));
        size_t b0 = (size_t)r0 * HID + cc + nd * 8;
        size_t b1 = (size_t)(r0 + 8) * HID + cc + nd * 8;
        *(__half2*)(g_AOh + b0) = h0;
        *(__half2*)(g_AOl + b0) = l0v;
        *(__half2*)(g_AOh + b1) = h1;
        *(__half2*)(g_AOl + b1) = l1v;
    }
}

// ---------------- final RMSNorm ----------------------------------------------
__global__ void final_norm_kernel(const float* __restrict__ sc, float* __restrict__ out)
{
    int s = blockIdx.x;
    const float* y = g_Y + (size_t)s * HID;
    float v = 0.0f;
    for (int d = threadIdx.x; d < HID; d += 256) { float x = y[d]; v += x * x; }
#pragma unroll
    for (int m = 16; m > 0; m >>= 1) v += __shfl_xor_sync(0xffffffffu, v, m);
    __shared__ float ws[8];
    if ((threadIdx.x & 31) == 0) ws[threadIdx.x >> 5] = v;
    __syncthreads();
    float tot = 0.0f;
#pragma unroll
    for (int i = 0; i < 8; i++) tot += ws[i];
    float inv = rsqrtf(tot * (1.0f / HID) + EPSV);
    for (int d = threadIdx.x; d < HID; d += 256)
        out[(size_t)s * HID + d] = y[d] * inv * sc[d];
}

// ---------------- launch -----------------------------------------------------
extern "C" void kernel_launch(void* const* d_in, const int* in_sizes, int n_in,
                              void* d_out, int out_size)
{
    const float* hidden = (const float*)d_in[0];
    const float* cosT   = (const float*)d_in[1];
    const float* sinT   = (const float*)d_in[2];
    const float* Wq     = (const float*)d_in[3];
    const float* Wk     = (const float*)d_in[4];
    const float* Wv     = (const float*)d_in[5];
    const float* Wo     = (const float*)d_in[6];
    const float* qs     = (const float*)d_in[7];
    const float* ks     = (const float*)d_in[8];
    const float* ls     = (const float*)d_in[9];
    float* out = (float*)d_out;

    cudaFuncSetAttribute(gemm_qkv, cudaFuncAttributeMaxDynamicSharedMemorySize, GEMM_SMEM);
    cudaFuncSetAttribute(gemm_wo,  cudaFuncAttributeMaxDynamicSharedMemorySize, GEMM_SMEM);
    cudaFuncSetAttribute(attn_mma, cudaFuncAttributeMaxDynamicSharedMemorySize, ATT_SMEM);

    // convert activations (fp16 split) + all weights (one launch)
    conv_act<<<SEQ * HID / 512, 256>>>(hidden);
    conv_wt_all<<<dim3(HID / 32, HID / 32, 4), dim3(32, 8)>>>(Wq, Wk, Wv, Wo);

    // fused QKV projection + RMSNorm + RoPE + fp16 outputs
    gemm_qkv<<<dim3(NQKV / 128, SEQ / 128), 256, GEMM_SMEM>>>(cosT, sinT, qs, ks);

    // causal GQA attention (single-fp16 Q and P)
    attn_mma<<<dim3(SEQ / 128, NH), 256, ATT_SMEM>>>();

    // output projection (fp16 2-term)
    gemm_wo<<<dim3(HID / 128, SEQ / 128), 256, GEMM_SMEM>>>();

    // final RMSNorm -> d_out
    final_norm_kernel<<<SEQ, 256>>>(ls, out);
}

// round 10
// speedup vs baseline: 1.5213x; 1.5213x over previous
#include <cuda_runtime.h>
#include <cuda_bf16.h>
#include <cuda_fp16.h>
#include <cstdint>
#include <math.h>

#define SEQ 2048
#define HID 2048
#define HD  128
#define NH  16
#define NKV 4
#define KVW (NKV*HD)           // 512
#define NQKV (HID + 2*KVW)     // 3072
#define EPSV 1e-6f
#define BKG 64
#define NSTG 4
#define KCH (HID / BKG)        // 32 k-chunks
#define GP  72                 // gemm smem row stride (halves)

// ---------------- scratch ----------------------------------------------------
__device__ float g_Y[SEQ * HID];

__device__ __half g_Ah[SEQ * HID];               // hidden split hi
__device__ __half g_Al[SEQ * HID];               // hidden split lo
__device__ __half g_AOh[SEQ * HID];              // attention-out split hi
__device__ __half g_AOl[SEQ * HID];
__device__ __half g_Wqkv[NQKV * HID];            // W^T fp16
__device__ __half g_Wo[HID * HID];

__device__ __half g_Qf[SEQ * HID];               // Q fp16 (post norm/rope)
__device__ __half g_Kf[SEQ * KVW];               // K fp16
__device__ __half g_Vf[SEQ * KVW];               // V fp16

// ======================= helpers =============================================
__device__ __forceinline__ uint32_t smem_u32(const void* p) {
    uint32_t a;
    asm("{ .reg .u64 t; cvta.to.shared.u64 t, %1; cvt.u32.u64 %0, t; }" : "=r"(a) : "l"(p));
    return a;
}
__device__ __forceinline__ void ldsm4(uint32_t* r, uint32_t addr) {
    asm volatile("ldmatrix.sync.aligned.m8n8.x4.shared.b16 {%0,%1,%2,%3}, [%4];"
        : "=r"(r[0]), "=r"(r[1]), "=r"(r[2]), "=r"(r[3]) : "r"(addr));
}
__device__ __forceinline__ void ldsm4t(uint32_t* r, uint32_t addr) {
    asm volatile("ldmatrix.sync.aligned.m8n8.x4.trans.shared.b16 {%0,%1,%2,%3}, [%4];"
        : "=r"(r[0]), "=r"(r[1]), "=r"(r[2]), "=r"(r[3]) : "r"(addr));
}
__device__ __forceinline__ void mma_f16(float* c, const uint32_t* a, const uint32_t* b) {
    asm volatile(
        "mma.sync.aligned.m16n8k16.row.col.f32.f16.f16.f32 "
        "{%0,%1,%2,%3}, {%4,%5,%6,%7}, {%8,%9}, {%0,%1,%2,%3};"
        : "+f"(c[0]), "+f"(c[1]), "+f"(c[2]), "+f"(c[3])
        : "r"(a[0]), "r"(a[1]), "r"(a[2]), "r"(a[3]), "r"(b[0]), "r"(b[1]));
}
__device__ __forceinline__ void cpa16(void* s, const void* g) {
    uint32_t sa = smem_u32(s);
    asm volatile("cp.async.cg.shared.global [%0], [%1], 16;" :: "r"(sa), "l"(g));
}

// ===== fp16 2-term GEMM core: C = (Ah+Al) @ B^T, 4-stage cp.async ===========
#define STAGE_HALF (3 * 128 * GP)
#define GEMM_SMEM  (NSTG * STAGE_HALF * 2)

struct GemmAcc { float a[4][4][4]; };

__device__ __forceinline__ void gemm_core(const __half* __restrict__ Ah,
                                          const __half* __restrict__ Al,
                                          const __half* __restrict__ B,
                                          int bm, int bn, __half* gs, GemmAcc& G)
{
    const int tid  = threadIdx.x;
    const int wid  = tid >> 5, lane = tid & 31;
    const int wm   = wid & 1, wn = wid >> 1;
    const uint32_t sbase = smem_u32(gs);

#define ISSUE(c) do {                                                                   \
    int _k0 = (c) * BKG;                                                                \
    __half* _sA = gs + ((c) % NSTG) * STAGE_HALF;                                       \
    __half* _sL = _sA + 128 * GP;                                                       \
    __half* _sB = _sL + 128 * GP;                                                       \
    _Pragma("unroll")                                                                   \
    for (int _i = 0; _i < 4; _i++) {                                                    \
        int _id = _i * 256 + tid; int _r = _id >> 3, _u = _id & 7;                      \
        int _so = _r * GP + _u * 8;                                                     \
        size_t _ga = (size_t)(bm + _r) * HID + _k0 + _u * 8;                            \
        cpa16(_sA + _so, Ah + _ga);                                                     \
        cpa16(_sL + _so, Al + _ga);                                                     \
        cpa16(_sB + _so, B + (size_t)(bn + _r) * HID + _k0 + _u * 8);                   \
    }                                                                                   \
    asm volatile("cp.async.commit_group;" ::: "memory");                                \
} while (0)

#pragma unroll
    for (int i = 0; i < 4; i++)
#pragma unroll
        for (int j = 0; j < 4; j++)
#pragma unroll
            for (int k = 0; k < 4; k++) G.a[i][j][k] = 0.0f;

    ISSUE(0); ISSUE(1); ISSUE(2);

    const uint32_t aOff = (uint32_t)((wm * 64 + (lane & 15)) * GP + ((lane >> 4) << 3)) * 2;
    const uint32_t bOff = (uint32_t)((wn * 32 + (lane & 7) + (((lane >> 4) & 1) << 3)) * GP
                                     + (((lane >> 3) & 1) << 3)) * 2;

    for (int c = 0; c < KCH; c++) {
        asm volatile("cp.async.wait_group 2;" ::: "memory");
        __syncthreads();
        if (c + 3 < KCH) { ISSUE(c + 3); }
        else { asm volatile("cp.async.commit_group;" ::: "memory"); }

        const uint32_t aB = sbase + (c % NSTG) * (STAGE_HALF * 2);
        const uint32_t lB = aB + 128 * GP * 2;
        const uint32_t bB = lB + 128 * GP * 2;
#pragma unroll
        for (int ks = 0; ks < 4; ks++) {
            uint32_t ah[4][4], al[4][4], bfr[2][4];
#pragma unroll
            for (int mi = 0; mi < 4; mi++) {
                ldsm4(ah[mi], aB + aOff + mi * (16 * GP * 2) + ks * 32);
                ldsm4(al[mi], lB + aOff + mi * (16 * GP * 2) + ks * 32);
            }
#pragma unroll
            for (int nj = 0; nj < 2; nj++)
                ldsm4(bfr[nj], bB + bOff + nj * (16 * GP * 2) + ks * 32);
#pragma unroll
            for (int mi = 0; mi < 4; mi++)
#pragma unroll
                for (int ni = 0; ni < 4; ni++) {
                    mma_f16(G.a[mi][ni], ah[mi], &bfr[ni >> 1][(ni & 1) * 2]);
                    mma_f16(G.a[mi][ni], al[mi], &bfr[ni >> 1][(ni & 1) * 2]);
                }
        }
    }
#undef ISSUE
}

// ---- fused QKV projection + per-head RMSNorm + RoPE + fp16 outputs ----------
__global__ __launch_bounds__(256) void gemm_qkv(const float* __restrict__ cosT,
                                                const float* __restrict__ sinT,
                                                const float* __restrict__ qscale,
                                                const float* __restrict__ kscale)
{
    extern __shared__ char dynsm[];
    GemmAcc G;
    const int bm = blockIdx.y * 128, bn = blockIdx.x * 128;
    gemm_core(g_Ah, g_Al, g_Wqkv, bm, bn, (__half*)dynsm, G);

    const int tid = threadIdx.x;
    const int lane = tid & 31, wid = tid >> 5;
    const int wm = wid & 1, wn = wid >> 1;

    asm volatile("cp.async.wait_group 0;" ::: "memory");
    __syncthreads();

    // ---- V tiles: plain fp16 store ----
    if (bn >= HID + KVW) {
        const int head = (bn - HID - KVW) >> 7;
#pragma unroll
        for (int mi = 0; mi < 4; mi++)
#pragma unroll
            for (int half = 0; half < 2; half++) {
                int s = bm + wm * 64 + mi * 16 + (lane >> 2) + half * 8;
#pragma unroll
                for (int ni = 0; ni < 4; ni++) {
                    int d = wn * 32 + (lane & 3) * 2 + ni * 8;
                    __half2 v = __floats2half2_rn(G.a[mi][ni][half * 2],
                                                  G.a[mi][ni][half * 2 + 1]);
                    *(__half2*)(g_Vf + (size_t)s * KVW + head * HD + d) = v;
                }
            }
        return;
    }

    // ---- Q / K tiles: RMSNorm + RoPE ----
    const bool isQ = (bn < HID);
    const int head = isQ ? (bn >> 7) : ((bn - HID) >> 7);
    const float* sc = isQ ? qscale : kscale;

    float* red = (float*)dynsm;
    float* stg = (float*)dynsm + 512 + 16;
#define STG(r, d) stg[(r) * 132 + (d)]

    float scv[4][2];
#pragma unroll
    for (int ni = 0; ni < 4; ni++) {
#pragma unroll
        for (int e2 = 0; e2 < 2; e2++)
            scv[ni][e2] = sc[wn * 32 + (lane & 3) * 2 + ni * 8 + e2];
    }

#pragma unroll
    for (int mi = 0; mi < 4; mi++) {
#pragma unroll
        for (int half = 0; half < 2; half++) {
            float p = 0.0f;
#pragma unroll
            for (int ni = 0; ni < 4; ni++) {
                float v0 = G.a[mi][ni][half * 2], v1 = G.a[mi][ni][half * 2 + 1];
                p += v0 * v0 + v1 * v1;
            }
            p += __shfl_xor_sync(0xffffffffu, p, 1);
            p += __shfl_xor_sync(0xffffffffu, p, 2);
            if ((lane & 3) == 0) {
                int r = wm * 64 + mi * 16 + (lane >> 2) + half * 8;
                red[r * 4 + wn] = p;
            }
        }
    }
    __syncthreads();

#pragma unroll
    for (int mi = 0; mi < 4; mi++) {
#pragma unroll
        for (int half = 0; half < 2; half++) {
            int r = wm * 64 + mi * 16 + (lane >> 2) + half * 8;
            float tot = red[r * 4] + red[r * 4 + 1] + red[r * 4 + 2] + red[r * 4 + 3];
            float inv = rsqrtf(tot * (1.0f / HD) + EPSV);
#pragma unroll
            for (int ni = 0; ni < 4; ni++) {
#pragma unroll
                for (int e2 = 0; e2 < 2; e2++) {
                    int d = wn * 32 + (lane & 3) * 2 + ni * 8 + e2;
                    float nv = G.a[mi][ni][half * 2 + e2] * inv * scv[ni][e2];
                    G.a[mi][ni][half * 2 + e2] = nv;
                    STG(r, d) = nv;
                }
            }
        }
    }
    __syncthreads();

#pragma unroll
    for (int mi = 0; mi < 4; mi++) {
#pragma unroll
        for (int half = 0; half < 2; half++) {
            int r = wm * 64 + mi * 16 + (lane >> 2) + half * 8;
            int s = bm + r;
#pragma unroll
            for (int ni = 0; ni < 4; ni++) {
                int d = wn * 32 + (lane & 3) * 2 + ni * 8;
                float nv0 = G.a[mi][ni][half * 2], nv1 = G.a[mi][ni][half * 2 + 1];
                float rot0, rot1;
                if (d < 64) { rot0 = -STG(r, d + 64); rot1 = -STG(r, d + 65); }
                else        { rot0 =  STG(r, d - 64); rot1 =  STG(r, d - 63); }
                float2 cv = *(const float2*)(cosT + (size_t)s * HD + d);
                float2 sv = *(const float2*)(sinT + (size_t)s * HD + d);
                float o0 = nv0 * cv.x + rot0 * sv.x;
                float o1 = nv1 * cv.y + rot1 * sv.y;
                __half2 hv = __floats2half2_rn(o0, o1);
                if (isQ) *(__half2*)(g_Qf + (size_t)s * HID + head * HD + d) = hv;
                else     *(__half2*)(g_Kf + (size_t)s * KVW + head * HD + d) = hv;
            }
        }
    }
#undef STG
}

// ---- Wo projection ----
__global__ __launch_bounds__(256) void gemm_wo()
{
    extern __shared__ char dynsm[];
    GemmAcc G;
    const int bm = blockIdx.y * 128, bn = blockIdx.x * 128;
    gemm_core(g_AOh, g_AOl, g_Wo, bm, bn, (__half*)dynsm, G);

    const int lane = threadIdx.x & 31, wid = threadIdx.x >> 5;
    const int cr = bm + (wid & 1) * 64 + (lane >> 2);
    const int cc = bn + (wid >> 1) * 32 + (lane & 3) * 2;
#pragma unroll
    for (int mi = 0; mi < 4; mi++)
#pragma unroll
        for (int ni = 0; ni < 4; ni++) {
            *(float2*)&g_Y[(size_t)(cr + mi * 16) * HID + cc + ni * 8] =
                make_float2(G.a[mi][ni][0], G.a[mi][ni][1]);
            *(float2*)&g_Y[(size_t)(cr + mi * 16 + 8) * HID + cc + ni * 8] =
                make_float2(G.a[mi][ni][2], G.a[mi][ni][3]);
        }
}

// =========== split-convert hidden: f32 -> Ah, Al fp16 ========================
__global__ void conv_act(const float* __restrict__ X)
{
    int idx = (blockIdx.x * blockDim.x + threadIdx.x) * 2;
    float2 x = *(const float2*)(X + idx);
    __half h0 = __float2half_rn(x.x);
    __half h1 = __float2half_rn(x.y);
    __half l0 = __float2half_rn(x.x - __half2float(h0));
    __half l1 = __float2half_rn(x.y - __half2float(h1));
    __half2 hv; hv.x = h0; hv.y = h1;
    __half2 lv; lv.x = l0; lv.y = l1;
    *(__half2*)(g_Ah + idx) = hv;
    *(__half2*)(g_Al + idx) = lv;
}

// ==== transpose all 4 weights: W[HID,N] f32 -> Wt[N,HID] fp16, one launch ====
__global__ void conv_wt_all(const float* __restrict__ Wq, const float* __restrict__ Wk,
                            const float* __restrict__ Wv, const float* __restrict__ Wo)
{
    __shared__ float t[32][33];
    const float* W; __half* Wt; int N;
    __half *wqkv = g_Wqkv, *wo = g_Wo;
    switch (blockIdx.z) {
        case 0: W = Wq; Wt = wqkv;                             N = HID; break;
        case 1: W = Wk; Wt = wqkv + (size_t)HID * HID;         N = KVW; break;
        case 2: W = Wv; Wt = wqkv + (size_t)(HID + KVW) * HID; N = KVW; break;
        default: W = Wo; Wt = wo;                              N = HID; break;
    }
    int n0 = blockIdx.x * 32, k0 = blockIdx.y * 32;
    if (n0 >= N) return;
    int tx = threadIdx.x, ty0 = threadIdx.y;
#pragma unroll
    for (int i = 0; i < 4; i++) {
        int ty = ty0 + i * 8;
        t[ty][tx] = W[(size_t)(k0 + ty) * N + n0 + tx];
    }
    __syncthreads();
#pragma unroll
    for (int i = 0; i < 4; i++) {
        int n = n0 + ty0 + i * 8;
        int k = k0 + tx;
        Wt[(size_t)n * HID + k] = __float2half_rn(t[tx][ty0 + i * 8]);
    }
}

// ---------------- causal GQA flash attention, fp16 single-term ---------------
// 256 threads = 8 warps; 128 q-rows; K/V 64-row tiles double-buffered.
// Q single fp16, P single fp16. NO occupancy forcing (R9 lesson: spills kill).
#define AP 136
#define KVBUF (2 * 64 * AP)
#define ATT_SMEM ((128 * AP + 2 * KVBUF) * 2)

__global__ __launch_bounds__(256) void attn_mma()
{
    extern __shared__ char dynsm[];
    __half* sm = (__half*)dynsm;
    __half* Qf = sm;
    __half* KV = sm + 128 * AP;

    const int qb = 15 - blockIdx.x;
    const int h  = blockIdx.y;
    const int kv = h >> 2;
    const int tid = threadIdx.x, w = tid >> 5, l = tid & 31;
    const float scl = 0.08838834764831845f;
    const int kmax = 2 * qb + 1;

    const __half* gkf = g_Kf + kv * HD;
    const __half* gvf = g_Vf + kv * HD;

#define ISSUE_KV(kb) do {                                                              \
    __half* _d = KV + ((kb) & 1) * KVBUF;                                              \
    size_t _g0 = (size_t)((kb) * 64) * KVW;                                            \
    _Pragma("unroll")                                                                  \
    for (int _i = 0; _i < 4; _i++) {                                                   \
        int _id = _i * 256 + tid; int _r = _id >> 4, _u = _id & 15;                    \
        size_t _go = _g0 + (size_t)_r * KVW + _u * 8;                                  \
        int _so = _r * AP + _u * 8;                                                    \
        cpa16(_d + _so,           gkf + _go);                                          \
        cpa16(_d + 64 * AP + _so, gvf + _go);                                          \
    }                                                                                  \
    asm volatile("cp.async.commit_group;" ::: "memory");                               \
} while (0)

    ISSUE_KV(0);

    {
        const __half* gq = g_Qf + (size_t)(qb * 128) * HID + h * HD;
#pragma unroll
        for (int i = 0; i < 8; i++) {
            int id = i * 256 + tid;
            int r = id >> 4, u = id & 15;
            *(uint4*)(Qf + r * AP + u * 8) = *(const uint4*)(gq + (size_t)r * HID + u * 8);
        }
    }

    const uint32_t qa = smem_u32(Qf);
    const uint32_t aOff = (uint32_t)((w * 16 + (l & 15)) * AP + ((l >> 4) << 3)) * 2;

    float m0 = -1e30f, m1 = -1e30f, ls0 = 0.0f, ls1 = 0.0f;
    float accO[16][4];
#pragma unroll
    for (int i = 0; i < 16; i++)
#pragma unroll
        for (int j = 0; j < 4; j++) accO[i][j] = 0.0f;

    for (int kb = 0; kb <= kmax; kb++) {
        asm volatile("cp.async.wait_group 0;" ::: "memory");
        __syncthreads();
        if (kb < kmax) ISSUE_KV(kb + 1);

        const __half* buf = KV + (kb & 1) * KVBUF;
        const uint32_t ka = smem_u32(buf);
        const uint32_t va = ka + 64 * AP * 2;

        // ---- S = Q · K (single fp16) ----
        float S[8][4];
#pragma unroll
        for (int t = 0; t < 8; t++)
#pragma unroll
            for (int e = 0; e < 4; e++) S[t][e] = 0.0f;

#pragma unroll
        for (int ks = 0; ks < 8; ks++) {
            uint32_t af[4], bf2[4][4];
            ldsm4(af, qa + aOff + ks * 32);
#pragma unroll
            for (int g = 0; g < 4; g++)
                ldsm4(bf2[g], ka + (uint32_t)((g * 16 + (l & 7) + (((l >> 4) & 1) << 3)) * AP
                                              + (((l >> 3) & 1) << 3)) * 2 + ks * 32);
#pragma unroll
            for (int t = 0; t < 8; t++)
                mma_f16(S[t], af, &bf2[t >> 1][(t & 1) * 2]);
        }

#pragma unroll
        for (int t = 0; t < 8; t++)
#pragma unroll
            for (int e = 0; e < 4; e++) S[t][e] *= scl;

        if (kb >= 2 * qb) {
            int r0 = qb * 128 + w * 16 + (l >> 2), r1 = r0 + 8;
            int cbase = kb * 64 + (l & 3) * 2;
#pragma unroll
            for (int t = 0; t < 8; t++) {
                int cb = cbase + t * 8;
                if (cb     > r0) S[t][0] = -1e30f;
                if (cb + 1 > r0) S[t][1] = -1e30f;
                if (cb     > r1) S[t][2] = -1e30f;
                if (cb + 1 > r1) S[t][3] = -1e30f;
            }
        }

        float mx0 = -1e30f, mx1 = -1e30f;
#pragma unroll
        for (int t = 0; t < 8; t++) {
            mx0 = fmaxf(mx0, fmaxf(S[t][0], S[t][1]));
            mx1 = fmaxf(mx1, fmaxf(S[t][2], S[t][3]));
        }
        mx0 = fmaxf(mx0, __shfl_xor_sync(0xffffffffu, mx0, 1));
        mx0 = fmaxf(mx0, __shfl_xor_sync(0xffffffffu, mx0, 2));
        mx1 = fmaxf(mx1, __shfl_xor_sync(0xffffffffu, mx1, 1));
        mx1 = fmaxf(mx1, __shfl_xor_sync(0xffffffffu, mx1, 2));

        float nm0 = fmaxf(m0, mx0), nm1 = fmaxf(m1, mx1);
        float cr0 = __expf(m0 - nm0), cr1 = __expf(m1 - nm1);
        m0 = nm0; m1 = nm1;
        ls0 *= cr0; ls1 *= cr1;
#pragma unroll
        for (int t = 0; t < 16; t++) {
            accO[t][0] *= cr0; accO[t][1] *= cr0;
            accO[t][2] *= cr1; accO[t][3] *= cr1;
        }

        // P = exp(S - m) -> single fp16 fragments
        uint32_t Pa[4][4];
        float rs0 = 0.0f, rs1 = 0.0f;
#pragma unroll
        for (int t = 0; t < 8; t++) {
            float p0 = __expf(S[t][0] - nm0), p1 = __expf(S[t][1] - nm0);
            float p2 = __expf(S[t][2] - nm1), p3 = __expf(S[t][3] - nm1);
            rs0 += p0 + p1; rs1 += p2 + p3;
            __half2 h01 = __floats2half2_rn(p0, p1);
            __half2 h23 = __floats2half2_rn(p2, p3);
            int kc = t >> 1, hi = (t & 1) * 2;
            Pa[kc][hi]     = *(uint32_t*)&h01;
            Pa[kc][hi + 1] = *(uint32_t*)&h23;
        }
        rs0 += __shfl_xor_sync(0xffffffffu, rs0, 1);
        rs0 += __shfl_xor_sync(0xffffffffu, rs0, 2);
        rs1 += __shfl_xor_sync(0xffffffffu, rs1, 1);
        rs1 += __shfl_xor_sync(0xffffffffu, rs1, 2);
        ls0 += rs0; ls1 += rs1;

        // ---- PV: acc += P · V ----
#pragma unroll
        for (int kc = 0; kc < 4; kc++) {
            uint32_t vb[8][4];
#pragma unroll
            for (int g = 0; g < 8; g++)
                ldsm4t(vb[g], va + (uint32_t)((kc * 16 + (l & 15)) * AP
                                              + (g * 16 + ((l >> 4) << 3))) * 2);
#pragma unroll
            for (int nd = 0; nd < 16; nd++)
                mma_f16(accO[nd], Pa[kc], &vb[nd >> 1][(nd & 1) * 2]);
        }
    }
#undef ISSUE_KV

    // epilogue: write AOh / AOl fp16 splits (Wo stays 2-term)
    float inv0 = 1.0f / ls0, inv1 = 1.0f / ls1;
    int r0 = qb * 128 + w * 16 + (l >> 2);
    int cc = h * HD + (l & 3) * 2;
#pragma unroll
    for (int nd = 0; nd < 16; nd++) {
        float v00 = accO[nd][0] * inv0, v01 = accO[nd][1] * inv0;
        float v10 = accO[nd][2] * inv1, v11 = accO[nd][3] * inv1;
        __half2 h0 = __floats2half2_rn(v00, v01);
        __half2 l0v = __floats2half2_rn(v00 - __half2float(h0.x), v01 - __half2float(h0.y));
        __half2 h1 = __floats2half2_rn(v10, v11);
        __half2 l1v = __floats2half2_rn(v10 - __half2float(h1.x), v11 - __half2float(h1.y));
        size_t b0 = (size_t)r0 * HID + cc + nd * 8;
        size_t b1 = (size_t)(r0 + 8) * HID + cc + nd * 8;
        *(__half2*)(g_AOh + b0) = h0;
        *(__half2*)(g_AOl + b0) = l0v;
        *(__half2*)(g_AOh + b1) = h1;
        *(__half2*)(g_AOl + b1) = l1v;
    }
}

// ---------------- final RMSNorm ----------------------------------------------
__global__ void final_norm_kernel(const float* __restrict__ sc, float* __restrict__ out)
{
    int s = blockIdx.x;
    const float* y = g_Y + (size_t)s * HID;
    float v = 0.0f;
    for (int d = threadIdx.x; d < HID; d += 256) { float x = y[d]; v += x * x; }
#pragma unroll
    for (int m = 16; m > 0; m >>= 1) v += __shfl_xor_sync(0xffffffffu, v, m);
    __shared__ float ws[8];
    if ((threadIdx.x & 31) == 0) ws[threadIdx.x >> 5] = v;
    __syncthreads();
    float tot = 0.0f;
#pragma unroll
    for (int i = 0; i < 8; i++) tot += ws[i];
    float inv = rsqrtf(tot * (1.0f / HID) + EPSV);
    for (int d = threadIdx.x; d < HID; d += 256)
        out[(size_t)s * HID + d] = y[d] * inv * sc[d];
}

// ---------------- launch -----------------------------------------------------
extern "C" void kernel_launch(void* const* d_in, const int* in_sizes, int n_in,
                              void* d_out, int out_size)
{
    const float* hidden = (const float*)d_in[0];
    const float* cosT   = (const float*)d_in[1];
    const float* sinT   = (const float*)d_in[2];
    const float* Wq     = (const float*)d_in[3];
    const float* Wk     = (const float*)d_in[4];
    const float* Wv     = (const float*)d_in[5];
    const float* Wo     = (const float*)d_in[6];
    const float* qs     = (const float*)d_in[7];
    const float* ks     = (const float*)d_in[8];
    const float* ls     = (const float*)d_in[9];
    float* out = (float*)d_out;

    cudaFuncSetAttribute(gemm_qkv, cudaFuncAttributeMaxDynamicSharedMemorySize, GEMM_SMEM);
    cudaFuncSetAttribute(gemm_wo,  cudaFuncAttributeMaxDynamicSharedMemorySize, GEMM_SMEM);
    cudaFuncSetAttribute(attn_mma, cudaFuncAttributeMaxDynamicSharedMemorySize, ATT_SMEM);

    // convert activations (fp16 split) + all weights (one launch)
    conv_act<<<SEQ * HID / 512, 256>>>(hidden);
    conv_wt_all<<<dim3(HID / 32, HID / 32, 4), dim3(32, 8)>>>(Wq, Wk, Wv, Wo);

    // fused QKV projection + RMSNorm + RoPE + fp16 outputs
    gemm_qkv<<<dim3(NQKV / 128, SEQ / 128), 256, GEMM_SMEM>>>(cosT, sinT, qs, ks);

    // causal GQA attention (single-fp16 Q and P, natural regs)
    attn_mma<<<dim3(SEQ / 128, NH), 256, ATT_SMEM>>>();

    // output projection (fp16 2-term)
    gemm_wo<<<dim3(HID / 128, SEQ / 128), 256, GEMM_SMEM>>>();

    // final RMSNorm -> d_out
    final_norm_kernel<<<SEQ, 256>>>(ls, out);
}

// round 11
// speedup vs baseline: 2.0355x; 1.3379x over previous
#include <cuda_runtime.h>
#include <cuda_bf16.h>
#include <cuda_fp16.h>
#include <cstdint>
#include <math.h>

#define SEQ 2048
#define HID 2048
#define HD  128
#define NH  16
#define NKV 4
#define KVW (NKV*HD)           // 512
#define NQKV (HID + 2*KVW)     // 3072
#define EPSV 1e-6f
#define BKG 64
#define NSTG 5
#define KCH (HID / BKG)        // 32 k-chunks
#define GP  72                 // gemm smem row stride (halves)

// ---------------- scratch ----------------------------------------------------
__device__ float g_Y[SEQ * HID];

__device__ __half g_Ah[SEQ * HID];               // hidden fp16
__device__ __half g_AOh[SEQ * HID];              // attention-out fp16
__device__ __half g_Wqkv[NQKV * HID];            // W^T fp16
__device__ __half g_Wo[HID * HID];

__device__ __half g_Qf[SEQ * HID];               // Q fp16 (post norm/rope)
__device__ __half g_Kf[SEQ * KVW];               // K fp16
__device__ __half g_Vf[SEQ * KVW];               // V fp16

// ======================= helpers =============================================
__device__ __forceinline__ uint32_t smem_u32(const void* p) {
    uint32_t a;
    asm("{ .reg .u64 t; cvta.to.shared.u64 t, %1; cvt.u32.u64 %0, t; }" : "=r"(a) : "l"(p));
    return a;
}
__device__ __forceinline__ void ldsm4(uint32_t* r, uint32_t addr) {
    asm volatile("ldmatrix.sync.aligned.m8n8.x4.shared.b16 {%0,%1,%2,%3}, [%4];"
        : "=r"(r[0]), "=r"(r[1]), "=r"(r[2]), "=r"(r[3]) : "r"(addr));
}
__device__ __forceinline__ void ldsm4t(uint32_t* r, uint32_t addr) {
    asm volatile("ldmatrix.sync.aligned.m8n8.x4.trans.shared.b16 {%0,%1,%2,%3}, [%4];"
        : "=r"(r[0]), "=r"(r[1]), "=r"(r[2]), "=r"(r[3]) : "r"(addr));
}
__device__ __forceinline__ void mma_f16(float* c, const uint32_t* a, const uint32_t* b) {
    asm volatile(
        "mma.sync.aligned.m16n8k16.row.col.f32.f16.f16.f32 "
        "{%0,%1,%2,%3}, {%4,%5,%6,%7}, {%8,%9}, {%0,%1,%2,%3};"
        : "+f"(c[0]), "+f"(c[1]), "+f"(c[2]), "+f"(c[3])
        : "r"(a[0]), "r"(a[1]), "r"(a[2]), "r"(a[3]), "r"(b[0]), "r"(b[1]));
}
__device__ __forceinline__ void cpa16(void* s, const void* g) {
    uint32_t sa = smem_u32(s);
    asm volatile("cp.async.cg.shared.global [%0], [%1], 16;" :: "r"(sa), "l"(g));
}

// ===== fp16 1-term GEMM core: C = A @ B^T, 5-stage cp.async =================
#define STAGE_HALF (2 * 128 * GP)
#define GEMM_SMEM  (NSTG * STAGE_HALF * 2)

struct GemmAcc { float a[4][4][4]; };

__device__ __forceinline__ void gemm_core(const __half* __restrict__ A,
                                          const __half* __restrict__ B,
                                          int bm, int bn, __half* gs, GemmAcc& G)
{
    const int tid  = threadIdx.x;
    const int wid  = tid >> 5, lane = tid & 31;
    const int wm   = wid & 1, wn = wid >> 1;
    const uint32_t sbase = smem_u32(gs);

#define ISSUE(c) do {                                                                   \
    int _k0 = (c) * BKG;                                                                \
    __half* _sA = gs + ((c) % NSTG) * STAGE_HALF;                                       \
    __half* _sB = _sA + 128 * GP;                                                       \
    _Pragma("unroll")                                                                   \
    for (int _i = 0; _i < 4; _i++) {                                                    \
        int _id = _i * 256 + tid; int _r = _id >> 3, _u = _id & 7;                      \
        int _so = _r * GP + _u * 8;                                                     \
        cpa16(_sA + _so, A + (size_t)(bm + _r) * HID + _k0 + _u * 8);                   \
        cpa16(_sB + _so, B + (size_t)(bn + _r) * HID + _k0 + _u * 8);                   \
    }                                                                                   \
    asm volatile("cp.async.commit_group;" ::: "memory");                                \
} while (0)

#pragma unroll
    for (int i = 0; i < 4; i++)
#pragma unroll
        for (int j = 0; j < 4; j++)
#pragma unroll
            for (int k = 0; k < 4; k++) G.a[i][j][k] = 0.0f;

    ISSUE(0); ISSUE(1); ISSUE(2); ISSUE(3);

    const uint32_t aOff = (uint32_t)((wm * 64 + (lane & 15)) * GP + ((lane >> 4) << 3)) * 2;
    const uint32_t bOff = (uint32_t)((wn * 32 + (lane & 7) + (((lane >> 4) & 1) << 3)) * GP
                                     + (((lane >> 3) & 1) << 3)) * 2;

    for (int c = 0; c < KCH; c++) {
        asm volatile("cp.async.wait_group 3;" ::: "memory");
        __syncthreads();
        if (c + 4 < KCH) { ISSUE(c + 4); }
        else { asm volatile("cp.async.commit_group;" ::: "memory"); }

        const uint32_t aB = sbase + (c % NSTG) * (STAGE_HALF * 2);
        const uint32_t bB = aB + 128 * GP * 2;
#pragma unroll
        for (int ks = 0; ks < 4; ks++) {
            uint32_t ah[4][4], bfr[2][4];
#pragma unroll
            for (int mi = 0; mi < 4; mi++)
                ldsm4(ah[mi], aB + aOff + mi * (16 * GP * 2) + ks * 32);
#pragma unroll
            for (int nj = 0; nj < 2; nj++)
                ldsm4(bfr[nj], bB + bOff + nj * (16 * GP * 2) + ks * 32);
#pragma unroll
            for (int mi = 0; mi < 4; mi++)
#pragma unroll
                for (int ni = 0; ni < 4; ni++)
                    mma_f16(G.a[mi][ni], ah[mi], &bfr[ni >> 1][(ni & 1) * 2]);
        }
    }
#undef ISSUE
}

// ---- fused QKV projection + per-head RMSNorm + RoPE + fp16 outputs ----------
__global__ __launch_bounds__(256) void gemm_qkv(const float* __restrict__ cosT,
                                                const float* __restrict__ sinT,
                                                const float* __restrict__ qscale,
                                                const float* __restrict__ kscale)
{
    extern __shared__ char dynsm[];
    GemmAcc G;
    const int bm = blockIdx.y * 128, bn = blockIdx.x * 128;
    gemm_core(g_Ah, g_Wqkv, bm, bn, (__half*)dynsm, G);

    const int tid = threadIdx.x;
    const int lane = tid & 31, wid = tid >> 5;
    const int wm = wid & 1, wn = wid >> 1;

    asm volatile("cp.async.wait_group 0;" ::: "memory");
    __syncthreads();

    // ---- V tiles: plain fp16 store ----
    if (bn >= HID + KVW) {
        const int head = (bn - HID - KVW) >> 7;
#pragma unroll
        for (int mi = 0; mi < 4; mi++)
#pragma unroll
            for (int half = 0; half < 2; half++) {
                int s = bm + wm * 64 + mi * 16 + (lane >> 2) + half * 8;
#pragma unroll
                for (int ni = 0; ni < 4; ni++) {
                    int d = wn * 32 + (lane & 3) * 2 + ni * 8;
                    __half2 v = __floats2half2_rn(G.a[mi][ni][half * 2],
                                                  G.a[mi][ni][half * 2 + 1]);
                    *(__half2*)(g_Vf + (size_t)s * KVW + head * HD + d) = v;
                }
            }
        return;
    }

    // ---- Q / K tiles: RMSNorm + RoPE ----
    const bool isQ = (bn < HID);
    const int head = isQ ? (bn >> 7) : ((bn - HID) >> 7);
    const float* sc = isQ ? qscale : kscale;

    float* red = (float*)dynsm;
    float* stg = (float*)dynsm + 512 + 16;
#define STG(r, d) stg[(r) * 132 + (d)]

    float scv[4][2];
#pragma unroll
    for (int ni = 0; ni < 4; ni++) {
#pragma unroll
        for (int e2 = 0; e2 < 2; e2++)
            scv[ni][e2] = sc[wn * 32 + (lane & 3) * 2 + ni * 8 + e2];
    }

#pragma unroll
    for (int mi = 0; mi < 4; mi++) {
#pragma unroll
        for (int half = 0; half < 2; half++) {
            float p = 0.0f;
#pragma unroll
            for (int ni = 0; ni < 4; ni++) {
                float v0 = G.a[mi][ni][half * 2], v1 = G.a[mi][ni][half * 2 + 1];
                p += v0 * v0 + v1 * v1;
            }
            p += __shfl_xor_sync(0xffffffffu, p, 1);
            p += __shfl_xor_sync(0xffffffffu, p, 2);
            if ((lane & 3) == 0) {
                int r = wm * 64 + mi * 16 + (lane >> 2) + half * 8;
                red[r * 4 + wn] = p;
            }
        }
    }
    __syncthreads();

#pragma unroll
    for (int mi = 0; mi < 4; mi++) {
#pragma unroll
        for (int half = 0; half < 2; half++) {
            int r = wm * 64 + mi * 16 + (lane >> 2) + half * 8;
            float tot = red[r * 4] + red[r * 4 + 1] + red[r * 4 + 2] + red[r * 4 + 3];
            float inv = rsqrtf(tot * (1.0f / HD) + EPSV);
#pragma unroll
            for (int ni = 0; ni < 4; ni++) {
#pragma unroll
                for (int e2 = 0; e2 < 2; e2++) {
                    int d = wn * 32 + (lane & 3) * 2 + ni * 8 + e2;
                    float nv = G.a[mi][ni][half * 2 + e2] * inv * scv[ni][e2];
                    G.a[mi][ni][half * 2 + e2] = nv;
                    STG(r, d) = nv;
                }
            }
        }
    }
    __syncthreads();

#pragma unroll
    for (int mi = 0; mi < 4; mi++) {
#pragma unroll
        for (int half = 0; half < 2; half++) {
            int r = wm * 64 + mi * 16 + (lane >> 2) + half * 8;
            int s = bm + r;
#pragma unroll
            for (int ni = 0; ni < 4; ni++) {
                int d = wn * 32 + (lane & 3) * 2 + ni * 8;
                float nv0 = G.a[mi][ni][half * 2], nv1 = G.a[mi][ni][half * 2 + 1];
                float rot0, rot1;
                if (d < 64) { rot0 = -STG(r, d + 64); rot1 = -STG(r, d + 65); }
                else        { rot0 =  STG(r, d - 64); rot1 =  STG(r, d - 63); }
                float2 cv = *(const float2*)(cosT + (size_t)s * HD + d);
                float2 sv = *(const float2*)(sinT + (size_t)s * HD + d);
                float o0 = nv0 * cv.x + rot0 * sv.x;
                float o1 = nv1 * cv.y + rot1 * sv.y;
                __half2 hv = __floats2half2_rn(o0, o1);
                if (isQ) *(__half2*)(g_Qf + (size_t)s * HID + head * HD + d) = hv;
                else     *(__half2*)(g_Kf + (size_t)s * KVW + head * HD + d) = hv;
            }
        }
    }
#undef STG
}

// ---- Wo projection ----
__global__ __launch_bounds__(256) void gemm_wo()
{
    extern __shared__ char dynsm[];
    GemmAcc G;
    const int bm = blockIdx.y * 128, bn = blockIdx.x * 128;
    gemm_core(g_AOh, g_Wo, bm, bn, (__half*)dynsm, G);

    const int lane = threadIdx.x & 31, wid = threadIdx.x >> 5;
    const int cr = bm + (wid & 1) * 64 + (lane >> 2);
    const int cc = bn + (wid >> 1) * 32 + (lane & 3) * 2;
#pragma unroll
    for (int mi = 0; mi < 4; mi++)
#pragma unroll
        for (int ni = 0; ni < 4; ni++) {
            *(float2*)&g_Y[(size_t)(cr + mi * 16) * HID + cc + ni * 8] =
                make_float2(G.a[mi][ni][0], G.a[mi][ni][1]);
            *(float2*)&g_Y[(size_t)(cr + mi * 16 + 8) * HID + cc + ni * 8] =
                make_float2(G.a[mi][ni][2], G.a[mi][ni][3]);
        }
}

// =========== convert hidden: f32 -> fp16 =====================================
__global__ void conv_act(const float* __restrict__ X)
{
    int idx = (blockIdx.x * blockDim.x + threadIdx.x) * 2;
    float2 x = *(const float2*)(X + idx);
    *(__half2*)(g_Ah + idx) = __floats2half2_rn(x.x, x.y);
}

// ==== transpose all 4 weights: W[HID,N] f32 -> Wt[N,HID] fp16, one launch ====
__global__ void conv_wt_all(const float* __restrict__ Wq, const float* __restrict__ Wk,
                            const float* __restrict__ Wv, const float* __restrict__ Wo)
{
    __shared__ float t[32][33];
    const float* W; __half* Wt; int N;
    __half *wqkv = g_Wqkv, *wo = g_Wo;
    switch (blockIdx.z) {
        case 0: W = Wq; Wt = wqkv;                             N = HID; break;
        case 1: W = Wk; Wt = wqkv + (size_t)HID * HID;         N = KVW; break;
        case 2: W = Wv; Wt = wqkv + (size_t)(HID + KVW) * HID; N = KVW; break;
        default: W = Wo; Wt = wo;                              N = HID; break;
    }
    int n0 = blockIdx.x * 32, k0 = blockIdx.y * 32;
    if (n0 >= N) return;
    int tx = threadIdx.x, ty0 = threadIdx.y;
#pragma unroll
    for (int i = 0; i < 4; i++) {
        int ty = ty0 + i * 8;
        t[ty][tx] = W[(size_t)(k0 + ty) * N + n0 + tx];
    }
    __syncthreads();
#pragma unroll
    for (int i = 0; i < 4; i++) {
        int n = n0 + ty0 + i * 8;
        int k = k0 + tx;
        Wt[(size_t)n * HID + k] = __float2half_rn(t[tx][ty0 + i * 8]);
    }
}

// ---------------- causal GQA flash attention, fp16 single-term ---------------
// 256 threads = 8 warps; 128 q-rows; K/V 64-row tiles double-buffered.
// Q single fp16, P single fp16. Natural register allocation (R9 lesson).
#define AP 136
#define KVBUF (2 * 64 * AP)
#define ATT_SMEM ((128 * AP + 2 * KVBUF) * 2)

__global__ __launch_bounds__(256) void attn_mma()
{
    extern __shared__ char dynsm[];
    __half* sm = (__half*)dynsm;
    __half* Qf = sm;
    __half* KV = sm + 128 * AP;

    const int qb = 15 - blockIdx.x;
    const int h  = blockIdx.y;
    const int kv = h >> 2;
    const int tid = threadIdx.x, w = tid >> 5, l = tid & 31;
    const float scl = 0.08838834764831845f;
    const int kmax = 2 * qb + 1;

    const __half* gkf = g_Kf + kv * HD;
    const __half* gvf = g_Vf + kv * HD;

#define ISSUE_KV(kb) do {                                                              \
    __half* _d = KV + ((kb) & 1) * KVBUF;                                              \
    size_t _g0 = (size_t)((kb) * 64) * KVW;                                            \
    _Pragma("unroll")                                                                  \
    for (int _i = 0; _i < 4; _i++) {                                                   \
        int _id = _i * 256 + tid; int _r = _id >> 4, _u = _id & 15;                    \
        size_t _go = _g0 + (size_t)_r * KVW + _u * 8;                                  \
        int _so = _r * AP + _u * 8;                                                    \
        cpa16(_d + _so,           gkf + _go);                                          \
        cpa16(_d + 64 * AP + _so, gvf + _go);                                          \
    }                                                                                  \
    asm volatile("cp.async.commit_group;" ::: "memory");                               \
} while (0)

    ISSUE_KV(0);

    {
        const __half* gq = g_Qf + (size_t)(qb * 128) * HID + h * HD;
#pragma unroll
        for (int i = 0; i < 8; i++) {
            int id = i * 256 + tid;
            int r = id >> 4, u = id & 15;
            *(uint4*)(Qf + r * AP + u * 8) = *(const uint4*)(gq + (size_t)r * HID + u * 8);
        }
    }

    const uint32_t qa = smem_u32(Qf);
    const uint32_t aOff = (uint32_t)((w * 16 + (l & 15)) * AP + ((l >> 4) << 3)) * 2;

    float m0 = -1e30f, m1 = -1e30f, ls0 = 0.0f, ls1 = 0.0f;
    float accO[16][4];
#pragma unroll
    for (int i = 0; i < 16; i++)
#pragma unroll
        for (int j = 0; j < 4; j++) accO[i][j] = 0.0f;

    for (int kb = 0; kb <= kmax; kb++) {
        asm volatile("cp.async.wait_group 0;" ::: "memory");
        __syncthreads();
        if (kb < kmax) ISSUE_KV(kb + 1);

        const __half* buf = KV + (kb & 1) * KVBUF;
        const uint32_t ka = smem_u32(buf);
        const uint32_t va = ka + 64 * AP * 2;

        // ---- S = Q · K ----
        float S[8][4];
#pragma unroll
        for (int t = 0; t < 8; t++)
#pragma unroll
            for (int e = 0; e < 4; e++) S[t][e] = 0.0f;

#pragma unroll
        for (int ks = 0; ks < 8; ks++) {
            uint32_t af[4], bf2[4][4];
            ldsm4(af, qa + aOff + ks * 32);
#pragma unroll
            for (int g = 0; g < 4; g++)
                ldsm4(bf2[g], ka + (uint32_t)((g * 16 + (l & 7) + (((l >> 4) & 1) << 3)) * AP
                                              + (((l >> 3) & 1) << 3)) * 2 + ks * 32);
#pragma unroll
            for (int t = 0; t < 8; t++)
                mma_f16(S[t], af, &bf2[t >> 1][(t & 1) * 2]);
        }

#pragma unroll
        for (int t = 0; t < 8; t++)
#pragma unroll
            for (int e = 0; e < 4; e++) S[t][e] *= scl;

        if (kb >= 2 * qb) {
            int r0 = qb * 128 + w * 16 + (l >> 2), r1 = r0 + 8;
            int cbase = kb * 64 + (l & 3) * 2;
#pragma unroll
            for (int t = 0; t < 8; t++) {
                int cb = cbase + t * 8;
                if (cb     > r0) S[t][0] = -1e30f;
                if (cb + 1 > r0) S[t][1] = -1e30f;
                if (cb     > r1) S[t][2] = -1e30f;
                if (cb + 1 > r1) S[t][3] = -1e30f;
            }
        }

        float mx0 = -1e30f, mx1 = -1e30f;
#pragma unroll
        for (int t = 0; t < 8; t++) {
            mx0 = fmaxf(mx0, fmaxf(S[t][0], S[t][1]));
            mx1 = fmaxf(mx1, fmaxf(S[t][2], S[t][3]));
        }
        mx0 = fmaxf(mx0, __shfl_xor_sync(0xffffffffu, mx0, 1));
        mx0 = fmaxf(mx0, __shfl_xor_sync(0xffffffffu, mx0, 2));
        mx1 = fmaxf(mx1, __shfl_xor_sync(0xffffffffu, mx1, 1));
        mx1 = fmaxf(mx1, __shfl_xor_sync(0xffffffffu, mx1, 2));

        float nm0 = fmaxf(m0, mx0), nm1 = fmaxf(m1, mx1);
        float cr0 = __expf(m0 - nm0), cr1 = __expf(m1 - nm1);
        m0 = nm0; m1 = nm1;
        ls0 *= cr0; ls1 *= cr1;
#pragma unroll
        for (int t = 0; t < 16; t++) {
            accO[t][0] *= cr0; accO[t][1] *= cr0;
            accO[t][2] *= cr1; accO[t][3] *= cr1;
        }

        uint32_t Pa[4][4];
        float rs0 = 0.0f, rs1 = 0.0f;
#pragma unroll
        for (int t = 0; t < 8; t++) {
            float p0 = __expf(S[t][0] - nm0), p1 = __expf(S[t][1] - nm0);
            float p2 = __expf(S[t][2] - nm1), p3 = __expf(S[t][3] - nm1);
            rs0 += p0 + p1; rs1 += p2 + p3;
            __half2 h01 = __floats2half2_rn(p0, p1);
            __half2 h23 = __floats2half2_rn(p2, p3);
            int kc = t >> 1, hi = (t & 1) * 2;
            Pa[kc][hi]     = *(uint32_t*)&h01;
            Pa[kc][hi + 1] = *(uint32_t*)&h23;
        }
        rs0 += __shfl_xor_sync(0xffffffffu, rs0, 1);
        rs0 += __shfl_xor_sync(0xffffffffu, rs0, 2);
        rs1 += __shfl_xor_sync(0xffffffffu, rs1, 1);
        rs1 += __shfl_xor_sync(0xffffffffu, rs1, 2);
        ls0 += rs0; ls1 += rs1;

        // ---- PV: acc += P · V ----
#pragma unroll
        for (int kc = 0; kc < 4; kc++) {
            uint32_t vb[8][4];
#pragma unroll
            for (int g = 0; g < 8; g++)
                ldsm4t(vb[g], va + (uint32_t)((kc * 16 + (l & 15)) * AP
                                              + (g * 16 + ((l >> 4) << 3))) * 2);
#pragma unroll
            for (int nd = 0; nd < 16; nd++)
                mma_f16(accO[nd], Pa[kc], &vb[nd >> 1][(nd & 1) * 2]);
        }
    }
#undef ISSUE_KV

    // epilogue: write AO fp16 (single term)
    float inv0 = 1.0f / ls0, inv1 = 1.0f / ls1;
    int r0 = qb * 128 + w * 16 + (l >> 2);
    int cc = h * HD + (l & 3) * 2;
#pragma unroll
    for (int nd = 0; nd < 16; nd++) {
        __half2 h0 = __floats2half2_rn(accO[nd][0] * inv0, accO[nd][1] * inv0);
        __half2 h1 = __floats2half2_rn(accO[nd][2] * inv1, accO[nd][3] * inv1);
        *(__half2*)(g_AOh + (size_t)r0 * HID + cc + nd * 8)       = h0;
        *(__half2*)(g_AOh + (size_t)(r0 + 8) * HID + cc + nd * 8) = h1;
    }
}

// ---------------- final RMSNorm ----------------------------------------------
__global__ void final_norm_kernel(const float* __restrict__ sc, float* __restrict__ out)
{
    int s = blockIdx.x;
    const float* y = g_Y + (size_t)s * HID;
    float v = 0.0f;
    for (int d = threadIdx.x; d < HID; d += 256) { float x = y[d]; v += x * x; }
#pragma unroll
    for (int m = 16; m > 0; m >>= 1) v += __shfl_xor_sync(0xffffffffu, v, m);
    __shared__ float ws[8];
    if ((threadIdx.x & 31) == 0) ws[threadIdx.x >> 5] = v;
    __syncthreads();
    float tot = 0.0f;
#pragma unroll
    for (int i = 0; i < 8; i++) tot += ws[i];
    float inv = rsqrtf(tot * (1.0f / HID) + EPSV);
    for (int d = threadIdx.x; d < HID; d += 256)
        out[(size_t)s * HID + d] = y[d] * inv * sc[d];
}

// ---------------- launch -----------------------------------------------------
extern "C" void kernel_launch(void* const* d_in, const int* in_sizes, int n_in,
                              void* d_out, int out_size)
{
    const float* hidden = (const float*)d_in[0];
    const float* cosT   = (const float*)d_in[1];
    const float* sinT   = (const float*)d_in[2];
    const float* Wq     = (const float*)d_in[3];
    const float* Wk     = (const float*)d_in[4];
    const float* Wv     = (const float*)d_in[5];
    const float* Wo     = (const float*)d_in[6];
    const float* qs     = (const float*)d_in[7];
    const float* ks     = (const float*)d_in[8];
    const float* ls     = (const float*)d_in[9];
    float* out = (float*)d_out;

    cudaFuncSetAttribute(gemm_qkv, cudaFuncAttributeMaxDynamicSharedMemorySize, GEMM_SMEM);
    cudaFuncSetAttribute(gemm_wo,  cudaFuncAttributeMaxDynamicSharedMemorySize, GEMM_SMEM);
    cudaFuncSetAttribute(attn_mma, cudaFuncAttributeMaxDynamicSharedMemorySize, ATT_SMEM);

    // convert activations + all weights to fp16
    conv_act<<<SEQ * HID / 512, 256>>>(hidden);
    conv_wt_all<<<dim3(HID / 32, HID / 32, 4), dim3(32, 8)>>>(Wq, Wk, Wv, Wo);

    // fused QKV projection + RMSNorm + RoPE (1-term fp16)
    gemm_qkv<<<dim3(NQKV / 128, SEQ / 128), 256, GEMM_SMEM>>>(cosT, sinT, qs, ks);

    // causal GQA attention (single-fp16 Q and P)
    attn_mma<<<dim3(SEQ / 128, NH), 256, ATT_SMEM>>>();

    // output projection (1-term fp16)
    gemm_wo<<<dim3(HID / 128, SEQ / 128), 256, GEMM_SMEM>>>();

    // final RMSNorm -> d_out
    final_norm_kernel<<<SEQ, 256>>>(ls, out);
}

// round 12
// speedup vs baseline: 2.0737x; 1.0188x over previous
#include <cuda_runtime.h>
#include <cuda_bf16.h>
#include <cuda_fp16.h>
#include <cstdint>
#include <math.h>

#define SEQ 2048
#define HID 2048
#define HD  128
#define NH  16
#define NKV 4
#define KVW (NKV*HD)           // 512
#define NQKV (HID + 2*KVW)     // 3072
#define EPSV 1e-6f
#define BKG 64
#define NSTG 5
#define KCH (HID / BKG)        // 32 k-chunks
#define GP  72                 // gemm smem row stride (halves)

// ---------------- scratch ----------------------------------------------------
__device__ float g_Y[SEQ * HID];

__device__ __half g_Ah[SEQ * HID];               // hidden fp16
__device__ __half g_AOh[SEQ * HID];              // attention-out fp16
__device__ __half g_Wqkv[NQKV * HID];            // W^T fp16
__device__ __half g_Wo[HID * HID];

__device__ __half g_Qf[SEQ * HID];               // Q fp16 (post norm/rope, pre-scaled)
__device__ __half g_Kf[SEQ * KVW];               // K fp16
__device__ __half g_Vf[SEQ * KVW];               // V fp16

// ======================= helpers =============================================
__device__ __forceinline__ uint32_t smem_u32(const void* p) {
    uint32_t a;
    asm("{ .reg .u64 t; cvta.to.shared.u64 t, %1; cvt.u32.u64 %0, t; }" : "=r"(a) : "l"(p));
    return a;
}
__device__ __forceinline__ void ldsm4(uint32_t* r, uint32_t addr) {
    asm volatile("ldmatrix.sync.aligned.m8n8.x4.shared.b16 {%0,%1,%2,%3}, [%4];"
        : "=r"(r[0]), "=r"(r[1]), "=r"(r[2]), "=r"(r[3]) : "r"(addr));
}
__device__ __forceinline__ void ldsm4t(uint32_t* r, uint32_t addr) {
    asm volatile("ldmatrix.sync.aligned.m8n8.x4.trans.shared.b16 {%0,%1,%2,%3}, [%4];"
        : "=r"(r[0]), "=r"(r[1]), "=r"(r[2]), "=r"(r[3]) : "r"(addr));
}
__device__ __forceinline__ void mma_f16(float* c, const uint32_t* a, const uint32_t* b) {
    asm volatile(
        "mma.sync.aligned.m16n8k16.row.col.f32.f16.f16.f32 "
        "{%0,%1,%2,%3}, {%4,%5,%6,%7}, {%8,%9}, {%0,%1,%2,%3};"
        : "+f"(c[0]), "+f"(c[1]), "+f"(c[2]), "+f"(c[3])
        : "r"(a[0]), "r"(a[1]), "r"(a[2]), "r"(a[3]), "r"(b[0]), "r"(b[1]));
}
__device__ __forceinline__ void cpa16(void* s, const void* g) {
    uint32_t sa = smem_u32(s);
    asm volatile("cp.async.cg.shared.global [%0], [%1], 16;" :: "r"(sa), "l"(g));
}

// ===== fp16 1-term GEMM core: C = A @ B^T, 5-stage cp.async =================
#define STAGE_HALF (2 * 128 * GP)
#define GEMM_SMEM  (NSTG * STAGE_HALF * 2)

struct GemmAcc { float a[4][4][4]; };

__device__ __forceinline__ void gemm_core(const __half* __restrict__ A,
                                          const __half* __restrict__ B,
                                          int bm, int bn, __half* gs, GemmAcc& G)
{
    const int tid  = threadIdx.x;
    const int wid  = tid >> 5, lane = tid & 31;
    const int wm   = wid & 1, wn = wid >> 1;
    const uint32_t sbase = smem_u32(gs);

#define ISSUE(c) do {                                                                   \
    int _k0 = (c) * BKG;                                                                \
    __half* _sA = gs + ((c) % NSTG) * STAGE_HALF;                                       \
    __half* _sB = _sA + 128 * GP;                                                       \
    _Pragma("unroll")                                                                   \
    for (int _i = 0; _i < 4; _i++) {                                                    \
        int _id = _i * 256 + tid; int _r = _id >> 3, _u = _id & 7;                      \
        int _so = _r * GP + _u * 8;                                                     \
        cpa16(_sA + _so, A + (size_t)(bm + _r) * HID + _k0 + _u * 8);                   \
        cpa16(_sB + _so, B + (size_t)(bn + _r) * HID + _k0 + _u * 8);                   \
    }                                                                                   \
    asm volatile("cp.async.commit_group;" ::: "memory");                                \
} while (0)

#pragma unroll
    for (int i = 0; i < 4; i++)
#pragma unroll
        for (int j = 0; j < 4; j++)
#pragma unroll
            for (int k = 0; k < 4; k++) G.a[i][j][k] = 0.0f;

    ISSUE(0); ISSUE(1); ISSUE(2); ISSUE(3);

    const uint32_t aOff = (uint32_t)((wm * 64 + (lane & 15)) * GP + ((lane >> 4) << 3)) * 2;
    const uint32_t bOff = (uint32_t)((wn * 32 + (lane & 7) + (((lane >> 4) & 1) << 3)) * GP
                                     + (((lane >> 3) & 1) << 3)) * 2;

    for (int c = 0; c < KCH; c++) {
        asm volatile("cp.async.wait_group 3;" ::: "memory");
        __syncthreads();
        if (c + 4 < KCH) { ISSUE(c + 4); }
        else { asm volatile("cp.async.commit_group;" ::: "memory"); }

        const uint32_t aB = sbase + (c % NSTG) * (STAGE_HALF * 2);
        const uint32_t bB = aB + 128 * GP * 2;
#pragma unroll
        for (int ks = 0; ks < 4; ks++) {
            uint32_t ah[4][4], bfr[2][4];
#pragma unroll
            for (int mi = 0; mi < 4; mi++)
                ldsm4(ah[mi], aB + aOff + mi * (16 * GP * 2) + ks * 32);
#pragma unroll
            for (int nj = 0; nj < 2; nj++)
                ldsm4(bfr[nj], bB + bOff + nj * (16 * GP * 2) + ks * 32);
#pragma unroll
            for (int mi = 0; mi < 4; mi++)
#pragma unroll
                for (int ni = 0; ni < 4; ni++)
                    mma_f16(G.a[mi][ni], ah[mi], &bfr[ni >> 1][(ni & 1) * 2]);
        }
    }
#undef ISSUE
}

// ---- fused QKV projection + per-head RMSNorm + RoPE + fp16 outputs ----------
// Q is pre-multiplied by 1/sqrt(HD) so attention needs no score scaling.
__global__ __launch_bounds__(256) void gemm_qkv(const float* __restrict__ cosT,
                                                const float* __restrict__ sinT,
                                                const float* __restrict__ qscale,
                                                const float* __restrict__ kscale)
{
    extern __shared__ char dynsm[];
    GemmAcc G;
    const int bm = blockIdx.y * 128, bn = blockIdx.x * 128;
    gemm_core(g_Ah, g_Wqkv, bm, bn, (__half*)dynsm, G);

    const int tid = threadIdx.x;
    const int lane = tid & 31, wid = tid >> 5;
    const int wm = wid & 1, wn = wid >> 1;

    asm volatile("cp.async.wait_group 0;" ::: "memory");
    __syncthreads();

    // ---- V tiles ----
    if (bn >= HID + KVW) {
        const int head = (bn - HID - KVW) >> 7;
#pragma unroll
        for (int mi = 0; mi < 4; mi++)
#pragma unroll
            for (int half = 0; half < 2; half++) {
                int s = bm + wm * 64 + mi * 16 + (lane >> 2) + half * 8;
#pragma unroll
                for (int ni = 0; ni < 4; ni++) {
                    int d = wn * 32 + (lane & 3) * 2 + ni * 8;
                    __half2 v = __floats2half2_rn(G.a[mi][ni][half * 2],
                                                  G.a[mi][ni][half * 2 + 1]);
                    *(__half2*)(g_Vf + (size_t)s * KVW + head * HD + d) = v;
                }
            }
        return;
    }

    // ---- Q / K tiles: RMSNorm + RoPE ----
    const bool isQ = (bn < HID);
    const int head = isQ ? (bn >> 7) : ((bn - HID) >> 7);
    const float* sc = isQ ? qscale : kscale;
    const float qmul = isQ ? 0.08838834764831845f : 1.0f;   // fold 1/sqrt(HD) into Q

    float* red = (float*)dynsm;
    float* stg = (float*)dynsm + 512 + 16;
#define STG(r, d) stg[(r) * 132 + (d)]

    float scv[4][2];
#pragma unroll
    for (int ni = 0; ni < 4; ni++) {
#pragma unroll
        for (int e2 = 0; e2 < 2; e2++)
            scv[ni][e2] = sc[wn * 32 + (lane & 3) * 2 + ni * 8 + e2];
    }

#pragma unroll
    for (int mi = 0; mi < 4; mi++) {
#pragma unroll
        for (int half = 0; half < 2; half++) {
            float p = 0.0f;
#pragma unroll
            for (int ni = 0; ni < 4; ni++) {
                float v0 = G.a[mi][ni][half * 2], v1 = G.a[mi][ni][half * 2 + 1];
                p += v0 * v0 + v1 * v1;
            }
            p += __shfl_xor_sync(0xffffffffu, p, 1);
            p += __shfl_xor_sync(0xffffffffu, p, 2);
            if ((lane & 3) == 0) {
                int r = wm * 64 + mi * 16 + (lane >> 2) + half * 8;
                red[r * 4 + wn] = p;
            }
        }
    }
    __syncthreads();

#pragma unroll
    for (int mi = 0; mi < 4; mi++) {
#pragma unroll
        for (int half = 0; half < 2; half++) {
            int r = wm * 64 + mi * 16 + (lane >> 2) + half * 8;
            float tot = red[r * 4] + red[r * 4 + 1] + red[r * 4 + 2] + red[r * 4 + 3];
            float inv = rsqrtf(tot * (1.0f / HD) + EPSV);
#pragma unroll
            for (int ni = 0; ni < 4; ni++) {
#pragma unroll
                for (int e2 = 0; e2 < 2; e2++) {
                    int d = wn * 32 + (lane & 3) * 2 + ni * 8 + e2;
                    float nv = G.a[mi][ni][half * 2 + e2] * inv * scv[ni][e2];
                    G.a[mi][ni][half * 2 + e2] = nv;
                    STG(r, d) = nv;
                }
            }
        }
    }
    __syncthreads();

#pragma unroll
    for (int mi = 0; mi < 4; mi++) {
#pragma unroll
        for (int half = 0; half < 2; half++) {
            int r = wm * 64 + mi * 16 + (lane >> 2) + half * 8;
            int s = bm + r;
#pragma unroll
            for (int ni = 0; ni < 4; ni++) {
                int d = wn * 32 + (lane & 3) * 2 + ni * 8;
                float nv0 = G.a[mi][ni][half * 2], nv1 = G.a[mi][ni][half * 2 + 1];
                float rot0, rot1;
                if (d < 64) { rot0 = -STG(r, d + 64); rot1 = -STG(r, d + 65); }
                else        { rot0 =  STG(r, d - 64); rot1 =  STG(r, d - 63); }
                float2 cv = *(const float2*)(cosT + (size_t)s * HD + d);
                float2 sv = *(const float2*)(sinT + (size_t)s * HD + d);
                float o0 = (nv0 * cv.x + rot0 * sv.x) * qmul;
                float o1 = (nv1 * cv.y + rot1 * sv.y) * qmul;
                __half2 hv = __floats2half2_rn(o0, o1);
                if (isQ) *(__half2*)(g_Qf + (size_t)s * HID + head * HD + d) = hv;
                else     *(__half2*)(g_Kf + (size_t)s * KVW + head * HD + d) = hv;
            }
        }
    }
#undef STG
}

// ---- Wo projection ----
__global__ __launch_bounds__(256) void gemm_wo()
{
    extern __shared__ char dynsm[];
    GemmAcc G;
    const int bm = blockIdx.y * 128, bn = blockIdx.x * 128;
    gemm_core(g_AOh, g_Wo, bm, bn, (__half*)dynsm, G);

    const int lane = threadIdx.x & 31, wid = threadIdx.x >> 5;
    const int cr = bm + (wid & 1) * 64 + (lane >> 2);
    const int cc = bn + (wid >> 1) * 32 + (lane & 3) * 2;
#pragma unroll
    for (int mi = 0; mi < 4; mi++)
#pragma unroll
        for (int ni = 0; ni < 4; ni++) {
            *(float2*)&g_Y[(size_t)(cr + mi * 16) * HID + cc + ni * 8] =
                make_float2(G.a[mi][ni][0], G.a[mi][ni][1]);
            *(float2*)&g_Y[(size_t)(cr + mi * 16 + 8) * HID + cc + ni * 8] =
                make_float2(G.a[mi][ni][2], G.a[mi][ni][3]);
        }
}

// =========== convert hidden: f32 -> fp16 =====================================
__global__ void conv_act(const float* __restrict__ X)
{
    int idx = (blockIdx.x * blockDim.x + threadIdx.x) * 2;
    float2 x = *(const float2*)(X + idx);
    *(__half2*)(g_Ah + idx) = __floats2half2_rn(x.x, x.y);
}

// ==== transpose all 4 weights: W[HID,N] f32 -> Wt[N,HID] fp16, one launch ====
__global__ void conv_wt_all(const float* __restrict__ Wq, const float* __restrict__ Wk,
                            const float* __restrict__ Wv, const float* __restrict__ Wo)
{
    __shared__ float t[32][33];
    const float* W; __half* Wt; int N;
    __half *wqkv = g_Wqkv, *wo = g_Wo;
    switch (blockIdx.z) {
        case 0: W = Wq; Wt = wqkv;                             N = HID; break;
        case 1: W = Wk; Wt = wqkv + (size_t)HID * HID;         N = KVW; break;
        case 2: W = Wv; Wt = wqkv + (size_t)(HID + KVW) * HID; N = KVW; break;
        default: W = Wo; Wt = wo;                              N = HID; break;
    }
    int n0 = blockIdx.x * 32, k0 = blockIdx.y * 32;
    if (n0 >= N) return;
    int tx = threadIdx.x, ty0 = threadIdx.y;
#pragma unroll
    for (int i = 0; i < 4; i++) {
        int ty = ty0 + i * 8;
        t[ty][tx] = W[(size_t)(k0 + ty) * N + n0 + tx];
    }
    __syncthreads();
#pragma unroll
    for (int i = 0; i < 4; i++) {
        int n = n0 + ty0 + i * 8;
        int k = k0 + tx;
        Wt[(size_t)n * HID + k] = __float2half_rn(t[tx][ty0 + i * 8]);
    }
}

// ---------------- causal GQA flash attention, fixed-offset softmax -----------
// Q pre-scaled by 1/sqrt(HD); RMSNorm bounds |s| <= 11.32, so P=exp(s-4) fits
// fp16 exactly over the whole possible score range: no online max needed.
#define AP 136
#define KVBUF (2 * 64 * AP)
#define ATT_SMEM ((128 * AP + 2 * KVBUF) * 2)
#define SOFF 4.0f

__global__ __launch_bounds__(256) void attn_mma()
{
    extern __shared__ char dynsm[];
    __half* sm = (__half*)dynsm;
    __half* Qf = sm;
    __half* KV = sm + 128 * AP;

    const int qb = 15 - blockIdx.x;
    const int h  = blockIdx.y;
    const int kv = h >> 2;
    const int tid = threadIdx.x, w = tid >> 5, l = tid & 31;
    const int kmax = 2 * qb + 1;

    const __half* gkf = g_Kf + kv * HD;
    const __half* gvf = g_Vf + kv * HD;

#define ISSUE_KV(kb) do {                                                              \
    __half* _d = KV + ((kb) & 1) * KVBUF;                                              \
    size_t _g0 = (size_t)((kb) * 64) * KVW;                                            \
    _Pragma("unroll")                                                                  \
    for (int _i = 0; _i < 4; _i++) {                                                   \
        int _id = _i * 256 + tid; int _r = _id >> 4, _u = _id & 15;                    \
        size_t _go = _g0 + (size_t)_r * KVW + _u * 8;                                  \
        int _so = _r * AP + _u * 8;                                                    \
        cpa16(_d + _so,           gkf + _go);                                          \
        cpa16(_d + 64 * AP + _so, gvf + _go);                                          \
    }                                                                                  \
    asm volatile("cp.async.commit_group;" ::: "memory");                               \
} while (0)

    ISSUE_KV(0);

    {
        const __half* gq = g_Qf + (size_t)(qb * 128) * HID + h * HD;
#pragma unroll
        for (int i = 0; i < 8; i++) {
            int id = i * 256 + tid;
            int r = id >> 4, u = id & 15;
            *(uint4*)(Qf + r * AP + u * 8) = *(const uint4*)(gq + (size_t)r * HID + u * 8);
        }
    }

    const uint32_t qa = smem_u32(Qf);
    const uint32_t aOff = (uint32_t)((w * 16 + (l & 15)) * AP + ((l >> 4) << 3)) * 2;

    float ls0 = 0.0f, ls1 = 0.0f;      // per-thread partial row sums
    float accO[16][4];
#pragma unroll
    for (int i = 0; i < 16; i++)
#pragma unroll
        for (int j = 0; j < 4; j++) accO[i][j] = 0.0f;

    for (int kb = 0; kb <= kmax; kb++) {
        asm volatile("cp.async.wait_group 0;" ::: "memory");
        __syncthreads();
        if (kb < kmax) ISSUE_KV(kb + 1);

        const __half* buf = KV + (kb & 1) * KVBUF;
        const uint32_t ka = smem_u32(buf);
        const uint32_t va = ka + 64 * AP * 2;

        // ---- S = Q · K (Q pre-scaled) ----
        float S[8][4];
#pragma unroll
        for (int t = 0; t < 8; t++)
#pragma unroll
            for (int e = 0; e < 4; e++) S[t][e] = 0.0f;

#pragma unroll
        for (int ks = 0; ks < 8; ks++) {
            uint32_t af[4], bf2[4][4];
            ldsm4(af, qa + aOff + ks * 32);
#pragma unroll
            for (int g = 0; g < 4; g++)
                ldsm4(bf2[g], ka + (uint32_t)((g * 16 + (l & 7) + (((l >> 4) & 1) << 3)) * AP
                                              + (((l >> 3) & 1) << 3)) * 2 + ks * 32);
#pragma unroll
            for (int t = 0; t < 8; t++)
                mma_f16(S[t], af, &bf2[t >> 1][(t & 1) * 2]);
        }

        if (kb >= 2 * qb) {
            int r0 = qb * 128 + w * 16 + (l >> 2), r1 = r0 + 8;
            int cbase = kb * 64 + (l & 3) * 2;
#pragma unroll
            for (int t = 0; t < 8; t++) {
                int cb = cbase + t * 8;
                if (cb     > r0) S[t][0] = -1e30f;
                if (cb + 1 > r0) S[t][1] = -1e30f;
                if (cb     > r1) S[t][2] = -1e30f;
                if (cb + 1 > r1) S[t][3] = -1e30f;
            }
        }

        // P = exp(S - SOFF), accumulate per-thread partial l, pack fp16
        uint32_t Pa[4][4];
#pragma unroll
        for (int t = 0; t < 8; t++) {
            float p0 = __expf(S[t][0] - SOFF), p1 = __expf(S[t][1] - SOFF);
            float p2 = __expf(S[t][2] - SOFF), p3 = __expf(S[t][3] - SOFF);
            ls0 += p0 + p1; ls1 += p2 + p3;
            __half2 h01 = __floats2half2_rn(p0, p1);
            __half2 h23 = __floats2half2_rn(p2, p3);
            int kc = t >> 1, hi = (t & 1) * 2;
            Pa[kc][hi]     = *(uint32_t*)&h01;
            Pa[kc][hi + 1] = *(uint32_t*)&h23;
        }

        // ---- PV: acc += P · V ----
#pragma unroll
        for (int kc = 0; kc < 4; kc++) {
            uint32_t vb[8][4];
#pragma unroll
            for (int g = 0; g < 8; g++)
                ldsm4t(vb[g], va + (uint32_t)((kc * 16 + (l & 15)) * AP
                                              + (g * 16 + ((l >> 4) << 3))) * 2);
#pragma unroll
            for (int nd = 0; nd < 16; nd++)
                mma_f16(accO[nd], Pa[kc], &vb[nd >> 1][(nd & 1) * 2]);
        }
    }
#undef ISSUE_KV

    // one-time row-sum reduction across the quad
    ls0 += __shfl_xor_sync(0xffffffffu, ls0, 1);
    ls0 += __shfl_xor_sync(0xffffffffu, ls0, 2);
    ls1 += __shfl_xor_sync(0xffffffffu, ls1, 1);
    ls1 += __shfl_xor_sync(0xffffffffu, ls1, 2);

    float inv0 = 1.0f / ls0, inv1 = 1.0f / ls1;
    int r0 = qb * 128 + w * 16 + (l >> 2);
    int cc = h * HD + (l & 3) * 2;
#pragma unroll
    for (int nd = 0; nd < 16; nd++) {
        __half2 h0 = __floats2half2_rn(accO[nd][0] * inv0, accO[nd][1] * inv0);
        __half2 h1 = __floats2half2_rn(accO[nd][2] * inv1, accO[nd][3] * inv1);
        *(__half2*)(g_AOh + (size_t)r0 * HID + cc + nd * 8)       = h0;
        *(__half2*)(g_AOh + (size_t)(r0 + 8) * HID + cc + nd * 8) = h1;
    }
}

// ---------------- final RMSNorm ----------------------------------------------
__global__ void final_norm_kernel(const float* __restrict__ sc, float* __restrict__ out)
{
    int s = blockIdx.x;
    const float* y = g_Y + (size_t)s * HID;
    float v = 0.0f;
    for (int d = threadIdx.x; d < HID; d += 256) { float x = y[d]; v += x * x; }
#pragma unroll
    for (int m = 16; m > 0; m >>= 1) v += __shfl_xor_sync(0xffffffffu, v, m);
    __shared__ float ws[8];
    if ((threadIdx.x & 31) == 0) ws[threadIdx.x >> 5] = v;
    __syncthreads();
    float tot = 0.0f;
#pragma unroll
    for (int i = 0; i < 8; i++) tot += ws[i];
    float inv = rsqrtf(tot * (1.0f / HID) + EPSV);
    for (int d = threadIdx.x; d < HID; d += 256)
        out[(size_t)s * HID + d] = y[d] * inv * sc[d];
}

// ---------------- launch -----------------------------------------------------
extern "C" void kernel_launch(void* const* d_in, const int* in_sizes, int n_in,
                              void* d_out, int out_size)
{
    const float* hidden = (const float*)d_in[0];
    const float* cosT   = (const float*)d_in[1];
    const float* sinT   = (const float*)d_in[2];
    const float* Wq     = (const float*)d_in[3];
    const float* Wk     = (const float*)d_in[4];
    const float* Wv     = (const float*)d_in[5];
    const float* Wo     = (const float*)d_in[6];
    const float* qs     = (const float*)d_in[7];
    const float* ks     = (const float*)d_in[8];
    const float* ls     = (const float*)d_in[9];
    float* out = (float*)d_out;

    cudaFuncSetAttribute(gemm_qkv, cudaFuncAttributeMaxDynamicSharedMemorySize, GEMM_SMEM);
    cudaFuncSetAttribute(gemm_wo,  cudaFuncAttributeMaxDynamicSharedMemorySize, GEMM_SMEM);
    cudaFuncSetAttribute(attn_mma, cudaFuncAttributeMaxDynamicSharedMemorySize, ATT_SMEM);

    // convert activations + all weights to fp16
    conv_act<<<SEQ * HID / 512, 256>>>(hidden);
    conv_wt_all<<<dim3(HID / 32, HID / 32, 4), dim3(32, 8)>>>(Wq, Wk, Wv, Wo);

    // fused QKV projection + RMSNorm + RoPE (Q pre-scaled)
    gemm_qkv<<<dim3(NQKV / 128, SEQ / 128), 256, GEMM_SMEM>>>(cosT, sinT, qs, ks);

    // causal GQA attention (fixed-offset softmax, single-fp16 Q/P)
    attn_mma<<<dim3(SEQ / 128, NH), 256, ATT_SMEM>>>();

    // output projection (1-term fp16)
    gemm_wo<<<dim3(HID / 128, SEQ / 128), 256, GEMM_SMEM>>>();

    // final RMSNorm -> d_out
    final_norm_kernel<<<SEQ, 256>>>(ls, out);
}

// round 13
// speedup vs baseline: 2.4002x; 1.1574x over previous
#include <cuda_runtime.h>
#include <cuda_bf16.h>
#include <cuda_fp16.h>
#include <cstdint>
#include <math.h>

#define SEQ 2048
#define HID 2048
#define HD  128
#define NH  16
#define NKV 4
#define KVW (NKV*HD)           // 512
#define NQKV (HID + 2*KVW)     // 3072
#define EPSV 1e-6f
#define BKG 64
#define NSTG 5
#define KCH (HID / BKG)        // 32 k-chunks
#define GP  72                 // gemm smem row stride (halves)

// ---------------- scratch ----------------------------------------------------
__device__ float g_Y[SEQ * HID];

__device__ __half g_Ah[SEQ * HID];               // hidden fp16
__device__ __half g_AOh[SEQ * HID];              // attention-out fp16
__device__ __half g_Wqkv[NQKV * HID];            // W^T fp16
__device__ __half g_Wo[HID * HID];

__device__ __half g_Qf[SEQ * HID];               // Q fp16 (post norm/rope, pre-scaled)
__device__ __half g_Kf[SEQ * KVW];               // K fp16
__device__ __half g_Vf[SEQ * KVW];               // V fp16

// split-K attention partials (A: split0/non-split; B: split1 rows >= 1024 only)
__device__ float g_AOa[SEQ * HID];
__device__ float g_AOb[SEQ * HID];
__device__ float g_La[SEQ * NH];
__device__ float g_Lb[SEQ * NH];

// work-item tables: 24 items/head, descending iteration count
__device__ const int ITEM_QB[24]  = {15,15, 7,14,14,13,13, 6,12,12,11,11, 5,10,10, 4, 9, 9, 8, 8, 3, 2, 1, 0};
__device__ const int ITEM_SPL[24] = { 0, 1, 0, 0, 1, 0, 1, 0, 0, 1, 0, 1, 0, 0, 1, 0, 0, 1, 0, 1, 0, 0, 0, 0};

// ======================= helpers =============================================
__device__ __forceinline__ uint32_t smem_u32(const void* p) {
    uint32_t a;
    asm("{ .reg .u64 t; cvta.to.shared.u64 t, %1; cvt.u32.u64 %0, t; }" : "=r"(a) : "l"(p));
    return a;
}
__device__ __forceinline__ void ldsm4(uint32_t* r, uint32_t addr) {
    asm volatile("ldmatrix.sync.aligned.m8n8.x4.shared.b16 {%0,%1,%2,%3}, [%4];"
        : "=r"(r[0]), "=r"(r[1]), "=r"(r[2]), "=r"(r[3]) : "r"(addr));
}
__device__ __forceinline__ void ldsm4t(uint32_t* r, uint32_t addr) {
    asm volatile("ldmatrix.sync.aligned.m8n8.x4.trans.shared.b16 {%0,%1,%2,%3}, [%4];"
        : "=r"(r[0]), "=r"(r[1]), "=r"(r[2]), "=r"(r[3]) : "r"(addr));
}
__device__ __forceinline__ void mma_f16(float* c, const uint32_t* a, const uint32_t* b) {
    asm volatile(
        "mma.sync.aligned.m16n8k16.row.col.f32.f16.f16.f32 "
        "{%0,%1,%2,%3}, {%4,%5,%6,%7}, {%8,%9}, {%0,%1,%2,%3};"
        : "+f"(c[0]), "+f"(c[1]), "+f"(c[2]), "+f"(c[3])
        : "r"(a[0]), "r"(a[1]), "r"(a[2]), "r"(a[3]), "r"(b[0]), "r"(b[1]));
}
__device__ __forceinline__ void cpa16(void* s, const void* g) {
    uint32_t sa = smem_u32(s);
    asm volatile("cp.async.cg.shared.global [%0], [%1], 16;" :: "r"(sa), "l"(g));
}

// ===== fp16 1-term GEMM core: C = A @ B^T, 5-stage cp.async =================
#define STAGE_HALF (2 * 128 * GP)
#define GEMM_SMEM  (NSTG * STAGE_HALF * 2)

struct GemmAcc { float a[4][4][4]; };

__device__ __forceinline__ void gemm_core(const __half* __restrict__ A,
                                          const __half* __restrict__ B,
                                          int bm, int bn, __half* gs, GemmAcc& G)
{
    const int tid  = threadIdx.x;
    const int wid  = tid >> 5, lane = tid & 31;
    const int wm   = wid & 1, wn = wid >> 1;
    const uint32_t sbase = smem_u32(gs);

#define ISSUE(c) do {                                                                   \
    int _k0 = (c) * BKG;                                                                \
    __half* _sA = gs + ((c) % NSTG) * STAGE_HALF;                                       \
    __half* _sB = _sA + 128 * GP;                                                       \
    _Pragma("unroll")                                                                   \
    for (int _i = 0; _i < 4; _i++) {                                                    \
        int _id = _i * 256 + tid; int _r = _id >> 3, _u = _id & 7;                      \
        int _so = _r * GP + _u * 8;                                                     \
        cpa16(_sA + _so, A + (size_t)(bm + _r) * HID + _k0 + _u * 8);                   \
        cpa16(_sB + _so, B + (size_t)(bn + _r) * HID + _k0 + _u * 8);                   \
    }                                                                                   \
    asm volatile("cp.async.commit_group;" ::: "memory");                                \
} while (0)

#pragma unroll
    for (int i = 0; i < 4; i++)
#pragma unroll
        for (int j = 0; j < 4; j++)
#pragma unroll
            for (int k = 0; k < 4; k++) G.a[i][j][k] = 0.0f;

    ISSUE(0); ISSUE(1); ISSUE(2); ISSUE(3);

    const uint32_t aOff = (uint32_t)((wm * 64 + (lane & 15)) * GP + ((lane >> 4) << 3)) * 2;
    const uint32_t bOff = (uint32_t)((wn * 32 + (lane & 7) + (((lane >> 4) & 1) << 3)) * GP
                                     + (((lane >> 3) & 1) << 3)) * 2;

    for (int c = 0; c < KCH; c++) {
        asm volatile("cp.async.wait_group 3;" ::: "memory");
        __syncthreads();
        if (c + 4 < KCH) { ISSUE(c + 4); }
        else { asm volatile("cp.async.commit_group;" ::: "memory"); }

        const uint32_t aB = sbase + (c % NSTG) * (STAGE_HALF * 2);
        const uint32_t bB = aB + 128 * GP * 2;
#pragma unroll
        for (int ks = 0; ks < 4; ks++) {
            uint32_t ah[4][4], bfr[2][4];
#pragma unroll
            for (int mi = 0; mi < 4; mi++)
                ldsm4(ah[mi], aB + aOff + mi * (16 * GP * 2) + ks * 32);
#pragma unroll
            for (int nj = 0; nj < 2; nj++)
                ldsm4(bfr[nj], bB + bOff + nj * (16 * GP * 2) + ks * 32);
#pragma unroll
            for (int mi = 0; mi < 4; mi++)
#pragma unroll
                for (int ni = 0; ni < 4; ni++)
                    mma_f16(G.a[mi][ni], ah[mi], &bfr[ni >> 1][(ni & 1) * 2]);
        }
    }
#undef ISSUE
}

// ---- fused QKV projection + per-head RMSNorm + RoPE + fp16 outputs ----------
__global__ __launch_bounds__(256) void gemm_qkv(const float* __restrict__ cosT,
                                                const float* __restrict__ sinT,
                                                const float* __restrict__ qscale,
                                                const float* __restrict__ kscale)
{
    extern __shared__ char dynsm[];
    GemmAcc G;
    const int bm = blockIdx.y * 128, bn = blockIdx.x * 128;
    gemm_core(g_Ah, g_Wqkv, bm, bn, (__half*)dynsm, G);

    const int tid = threadIdx.x;
    const int lane = tid & 31, wid = tid >> 5;
    const int wm = wid & 1, wn = wid >> 1;

    asm volatile("cp.async.wait_group 0;" ::: "memory");
    __syncthreads();

    // ---- V tiles ----
    if (bn >= HID + KVW) {
        const int head = (bn - HID - KVW) >> 7;
#pragma unroll
        for (int mi = 0; mi < 4; mi++)
#pragma unroll
            for (int half = 0; half < 2; half++) {
                int s = bm + wm * 64 + mi * 16 + (lane >> 2) + half * 8;
#pragma unroll
                for (int ni = 0; ni < 4; ni++) {
                    int d = wn * 32 + (lane & 3) * 2 + ni * 8;
                    __half2 v = __floats2half2_rn(G.a[mi][ni][half * 2],
                                                  G.a[mi][ni][half * 2 + 1]);
                    *(__half2*)(g_Vf + (size_t)s * KVW + head * HD + d) = v;
                }
            }
        return;
    }

    // ---- Q / K tiles: RMSNorm + RoPE ----
    const bool isQ = (bn < HID);
    const int head = isQ ? (bn >> 7) : ((bn - HID) >> 7);
    const float* sc = isQ ? qscale : kscale;
    const float qmul = isQ ? 0.08838834764831845f : 1.0f;

    float* red = (float*)dynsm;
    float* stg = (float*)dynsm + 512 + 16;
#define STG(r, d) stg[(r) * 132 + (d)]

    float scv[4][2];
#pragma unroll
    for (int ni = 0; ni < 4; ni++) {
#pragma unroll
        for (int e2 = 0; e2 < 2; e2++)
            scv[ni][e2] = sc[wn * 32 + (lane & 3) * 2 + ni * 8 + e2];
    }

#pragma unroll
    for (int mi = 0; mi < 4; mi++) {
#pragma unroll
        for (int half = 0; half < 2; half++) {
            float p = 0.0f;
#pragma unroll
            for (int ni = 0; ni < 4; ni++) {
                float v0 = G.a[mi][ni][half * 2], v1 = G.a[mi][ni][half * 2 + 1];
                p += v0 * v0 + v1 * v1;
            }
            p += __shfl_xor_sync(0xffffffffu, p, 1);
            p += __shfl_xor_sync(0xffffffffu, p, 2);
            if ((lane & 3) == 0) {
                int r = wm * 64 + mi * 16 + (lane >> 2) + half * 8;
                red[r * 4 + wn] = p;
            }
        }
    }
    __syncthreads();

#pragma unroll
    for (int mi = 0; mi < 4; mi++) {
#pragma unroll
        for (int half = 0; half < 2; half++) {
            int r = wm * 64 + mi * 16 + (lane >> 2) + half * 8;
            float tot = red[r * 4] + red[r * 4 + 1] + red[r * 4 + 2] + red[r * 4 + 3];
            float inv = rsqrtf(tot * (1.0f / HD) + EPSV);
#pragma unroll
            for (int ni = 0; ni < 4; ni++) {
#pragma unroll
                for (int e2 = 0; e2 < 2; e2++) {
                    int d = wn * 32 + (lane & 3) * 2 + ni * 8 + e2;
                    float nv = G.a[mi][ni][half * 2 + e2] * inv * scv[ni][e2];
                    G.a[mi][ni][half * 2 + e2] = nv;
                    STG(r, d) = nv;
                }
            }
        }
    }
    __syncthreads();

#pragma unroll
    for (int mi = 0; mi < 4; mi++) {
#pragma unroll
        for (int half = 0; half < 2; half++) {
            int r = wm * 64 + mi * 16 + (lane >> 2) + half * 8;
            int s = bm + r;
#pragma unroll
            for (int ni = 0; ni < 4; ni++) {
                int d = wn * 32 + (lane & 3) * 2 + ni * 8;
                float nv0 = G.a[mi][ni][half * 2], nv1 = G.a[mi][ni][half * 2 + 1];
                float rot0, rot1;
                if (d < 64) { rot0 = -STG(r, d + 64); rot1 = -STG(r, d + 65); }
                else        { rot0 =  STG(r, d - 64); rot1 =  STG(r, d - 63); }
                float2 cv = *(const float2*)(cosT + (size_t)s * HD + d);
                float2 sv = *(const float2*)(sinT + (size_t)s * HD + d);
                float o0 = (nv0 * cv.x + rot0 * sv.x) * qmul;
                float o1 = (nv1 * cv.y + rot1 * sv.y) * qmul;
                __half2 hv = __floats2half2_rn(o0, o1);
                if (isQ) *(__half2*)(g_Qf + (size_t)s * HID + head * HD + d) = hv;
                else     *(__half2*)(g_Kf + (size_t)s * KVW + head * HD + d) = hv;
            }
        }
    }
#undef STG
}

// ---- Wo projection ----
__global__ __launch_bounds__(256) void gemm_wo()
{
    extern __shared__ char dynsm[];
    GemmAcc G;
    const int bm = blockIdx.y * 128, bn = blockIdx.x * 128;
    gemm_core(g_AOh, g_Wo, bm, bn, (__half*)dynsm, G);

    const int lane = threadIdx.x & 31, wid = threadIdx.x >> 5;
    const int cr = bm + (wid & 1) * 64 + (lane >> 2);
    const int cc = bn + (wid >> 1) * 32 + (lane & 3) * 2;
#pragma unroll
    for (int mi = 0; mi < 4; mi++)
#pragma unroll
        for (int ni = 0; ni < 4; ni++) {
            *(float2*)&g_Y[(size_t)(cr + mi * 16) * HID + cc + ni * 8] =
                make_float2(G.a[mi][ni][0], G.a[mi][ni][1]);
            *(float2*)&g_Y[(size_t)(cr + mi * 16 + 8) * HID + cc + ni * 8] =
                make_float2(G.a[mi][ni][2], G.a[mi][ni][3]);
        }
}

// =========== convert hidden: f32 -> fp16 =====================================
__global__ void conv_act(const float* __restrict__ X)
{
    int idx = (blockIdx.x * blockDim.x + threadIdx.x) * 2;
    float2 x = *(const float2*)(X + idx);
    *(__half2*)(g_Ah + idx) = __floats2half2_rn(x.x, x.y);
}

// ==== transpose all 4 weights: W[HID,N] f32 -> Wt[N,HID] fp16, one launch ====
__global__ void conv_wt_all(const float* __restrict__ Wq, const float* __restrict__ Wk,
                            const float* __restrict__ Wv, const float* __restrict__ Wo)
{
    __shared__ float t[32][33];
    const float* W; __half* Wt; int N;
    __half *wqkv = g_Wqkv, *wo = g_Wo;
    switch (blockIdx.z) {
        case 0: W = Wq; Wt = wqkv;                             N = HID; break;
        case 1: W = Wk; Wt = wqkv + (size_t)HID * HID;         N = KVW; break;
        case 2: W = Wv; Wt = wqkv + (size_t)(HID + KVW) * HID; N = KVW; break;
        default: W = Wo; Wt = wo;                              N = HID; break;
    }
    int n0 = blockIdx.x * 32, k0 = blockIdx.y * 32;
    if (n0 >= N) return;
    int tx = threadIdx.x, ty0 = threadIdx.y;
#pragma unroll
    for (int i = 0; i < 4; i++) {
        int ty = ty0 + i * 8;
        t[ty][tx] = W[(size_t)(k0 + ty) * N + n0 + tx];
    }
    __syncthreads();
#pragma unroll
    for (int i = 0; i < 4; i++) {
        int n = n0 + ty0 + i * 8;
        int k = k0 + tx;
        Wt[(size_t)n * HID + k] = __float2half_rn(t[tx][ty0 + i * 8]);
    }
}

// ---------------- causal GQA attention: split-K, fixed-offset softmax --------
// grid (NH, 24): 24 work items per head (tables above, biggest first).
// qb<8: whole K-range -> buffers A. qb>=8: split0 kb[0..qb] -> A, split1
// kb[qb+1..2qb+1] -> B. Merge = pure sum (no max tracking).
#define AP 136
#define KVBUF (2 * 64 * AP)
#define ATT_SMEM ((128 * AP + 2 * KVBUF) * 2)
#define SOFF 4.0f

__global__ __launch_bounds__(256) void attn_mma()
{
    extern __shared__ char dynsm[];
    __half* sm = (__half*)dynsm;
    __half* Qf = sm;
    __half* KV = sm + 128 * AP;

    const int h    = blockIdx.x;
    const int item = blockIdx.y;
    const int qb   = ITEM_QB[item];
    const int spl  = ITEM_SPL[item];
    const bool isSplit = (qb >= 8);
    const int klo = (isSplit && spl == 1) ? (qb + 1) : 0;
    const int khi = (isSplit && spl == 0) ? qb : (2 * qb + 1);

    const int kv = h >> 2;
    const int tid = threadIdx.x, w = tid >> 5, l = tid & 31;

    const __half* gkf = g_Kf + kv * HD;
    const __half* gvf = g_Vf + kv * HD;

#define ISSUE_KV(kb) do {                                                              \
    __half* _d = KV + ((kb) & 1) * KVBUF;                                              \
    size_t _g0 = (size_t)((kb) * 64) * KVW;                                            \
    _Pragma("unroll")                                                                  \
    for (int _i = 0; _i < 4; _i++) {                                                   \
        int _id = _i * 256 + tid; int _r = _id >> 4, _u = _id & 15;                    \
        size_t _go = _g0 + (size_t)_r * KVW + _u * 8;                                  \
        int _so = _r * AP + _u * 8;                                                    \
        cpa16(_d + _so,           gkf + _go);                                          \
        cpa16(_d + 64 * AP + _so, gvf + _go);                                          \
    }                                                                                  \
    asm volatile("cp.async.commit_group;" ::: "memory");                               \
} while (0)

    ISSUE_KV(klo);

    {
        const __half* gq = g_Qf + (size_t)(qb * 128) * HID + h * HD;
#pragma unroll
        for (int i = 0; i < 8; i++) {
            int id = i * 256 + tid;
            int r = id >> 4, u = id & 15;
            *(uint4*)(Qf + r * AP + u * 8) = *(const uint4*)(gq + (size_t)r * HID + u * 8);
        }
    }

    const uint32_t qa = smem_u32(Qf);
    const uint32_t aOff = (uint32_t)((w * 16 + (l & 15)) * AP + ((l >> 4) << 3)) * 2;

    float ls0 = 0.0f, ls1 = 0.0f;
    float accO[16][4];
#pragma unroll
    for (int i = 0; i < 16; i++)
#pragma unroll
        for (int j = 0; j < 4; j++) accO[i][j] = 0.0f;

    for (int kb = klo; kb <= khi; kb++) {
        asm volatile("cp.async.wait_group 0;" ::: "memory");
        __syncthreads();
        if (kb < khi) ISSUE_KV(kb + 1);

        const __half* buf = KV + (kb & 1) * KVBUF;
        const uint32_t ka = smem_u32(buf);
        const uint32_t va = ka + 64 * AP * 2;

        float S[8][4];
#pragma unroll
        for (int t = 0; t < 8; t++)
#pragma unroll
            for (int e = 0; e < 4; e++) S[t][e] = 0.0f;

#pragma unroll
        for (int ks = 0; ks < 8; ks++) {
            uint32_t af[4], bf2[4][4];
            ldsm4(af, qa + aOff + ks * 32);
#pragma unroll
            for (int g = 0; g < 4; g++)
                ldsm4(bf2[g], ka + (uint32_t)((g * 16 + (l & 7) + (((l >> 4) & 1) << 3)) * AP
                                              + (((l >> 3) & 1) << 3)) * 2 + ks * 32);
#pragma unroll
            for (int t = 0; t < 8; t++)
                mma_f16(S[t], af, &bf2[t >> 1][(t & 1) * 2]);
        }

        if (kb >= 2 * qb) {
            int r0 = qb * 128 + w * 16 + (l >> 2), r1 = r0 + 8;
            int cbase = kb * 64 + (l & 3) * 2;
#pragma unroll
            for (int t = 0; t < 8; t++) {
                int cb = cbase + t * 8;
                if (cb     > r0) S[t][0] = -1e30f;
                if (cb + 1 > r0) S[t][1] = -1e30f;
                if (cb     > r1) S[t][2] = -1e30f;
                if (cb + 1 > r1) S[t][3] = -1e30f;
            }
        }

        uint32_t Pa[4][4];
#pragma unroll
        for (int t = 0; t < 8; t++) {
            float p0 = __expf(S[t][0] - SOFF), p1 = __expf(S[t][1] - SOFF);
            float p2 = __expf(S[t][2] - SOFF), p3 = __expf(S[t][3] - SOFF);
            ls0 += p0 + p1; ls1 += p2 + p3;
            __half2 h01 = __floats2half2_rn(p0, p1);
            __half2 h23 = __floats2half2_rn(p2, p3);
            int kc = t >> 1, hi = (t & 1) * 2;
            Pa[kc][hi]     = *(uint32_t*)&h01;
            Pa[kc][hi + 1] = *(uint32_t*)&h23;
        }

#pragma unroll
        for (int kc = 0; kc < 4; kc++) {
            uint32_t vb[8][4];
#pragma unroll
            for (int g = 0; g < 8; g++)
                ldsm4t(vb[g], va + (uint32_t)((kc * 16 + (l & 15)) * AP
                                              + (g * 16 + ((l >> 4) << 3))) * 2);
#pragma unroll
            for (int nd = 0; nd < 16; nd++)
                mma_f16(accO[nd], Pa[kc], &vb[nd >> 1][(nd & 1) * 2]);
        }
    }
#undef ISSUE_KV

    // reduce l over quad, write f32 partials (no normalization here)
    ls0 += __shfl_xor_sync(0xffffffffu, ls0, 1);
    ls0 += __shfl_xor_sync(0xffffffffu, ls0, 2);
    ls1 += __shfl_xor_sync(0xffffffffu, ls1, 1);
    ls1 += __shfl_xor_sync(0xffffffffu, ls1, 2);

    float* dstA = (isSplit && spl == 1) ? g_AOb : g_AOa;
    float* dstL = (isSplit && spl == 1) ? g_Lb  : g_La;

    int r0 = qb * 128 + w * 16 + (l >> 2);
    int cc = h * HD + (l & 3) * 2;
    if ((l & 3) == 0) {
        dstL[(size_t)r0 * NH + h]       = ls0;
        dstL[(size_t)(r0 + 8) * NH + h] = ls1;
    }
#pragma unroll
    for (int nd = 0; nd < 16; nd++) {
        *(float2*)(dstA + (size_t)r0 * HID + cc + nd * 8) =
            make_float2(accO[nd][0], accO[nd][1]);
        *(float2*)(dstA + (size_t)(r0 + 8) * HID + cc + nd * 8) =
            make_float2(accO[nd][2], accO[nd][3]);
    }
}

// ---- merge + normalize: AOh = (A [+ B]) / (La [+ Lb]) -----------------------
__global__ void attn_norm()
{
    int idx = (blockIdx.x * 256 + threadIdx.x) * 8;
    int s = idx >> 11;               // / HID
    int h = (idx & (HID - 1)) >> 7;  // / HD
    bool hasB = (s >= 1024);         // qb >= 8 rows were split

    float lsum = g_La[(size_t)s * NH + h] + (hasB ? g_Lb[(size_t)s * NH + h] : 0.0f);
    float inv = 1.0f / lsum;

    float4 a0 = *(float4*)(g_AOa + idx);
    float4 a1 = *(float4*)(g_AOa + idx + 4);
    if (hasB) {
        float4 b0 = *(float4*)(g_AOb + idx);
        float4 b1 = *(float4*)(g_AOb + idx + 4);
        a0.x += b0.x; a0.y += b0.y; a0.z += b0.z; a0.w += b0.w;
        a1.x += b1.x; a1.y += b1.y; a1.z += b1.z; a1.w += b1.w;
    }
    __half2 o0 = __floats2half2_rn(a0.x * inv, a0.y * inv);
    __half2 o1 = __floats2half2_rn(a0.z * inv, a0.w * inv);
    __half2 o2 = __floats2half2_rn(a1.x * inv, a1.y * inv);
    __half2 o3 = __floats2half2_rn(a1.z * inv, a1.w * inv);
    *(__half2*)(g_AOh + idx)     = o0;
    *(__half2*)(g_AOh + idx + 2) = o1;
    *(__half2*)(g_AOh + idx + 4) = o2;
    *(__half2*)(g_AOh + idx + 6) = o3;
}

// ---------------- final RMSNorm ----------------------------------------------
__global__ void final_norm_kernel(const float* __restrict__ sc, float* __restrict__ out)
{
    int s = blockIdx.x;
    const float* y = g_Y + (size_t)s * HID;
    float v = 0.0f;
    for (int d = threadIdx.x; d < HID; d += 256) { float x = y[d]; v += x * x; }
#pragma unroll
    for (int m = 16; m > 0; m >>= 1) v += __shfl_xor_sync(0xffffffffu, v, m);
    __shared__ float ws[8];
    if ((threadIdx.x & 31) == 0) ws[threadIdx.x >> 5] = v;
    __syncthreads();
    float tot = 0.0f;
#pragma unroll
    for (int i = 0; i < 8; i++) tot += ws[i];
    float inv = rsqrtf(tot * (1.0f / HID) + EPSV);
    for (int d = threadIdx.x; d < HID; d += 256)
        out[(size_t)s * HID + d] = y[d] * inv * sc[d];
}

// ---------------- launch -----------------------------------------------------
extern "C" void kernel_launch(void* const* d_in, const int* in_sizes, int n_in,
                              void* d_out, int out_size)
{
    const float* hidden = (const float*)d_in[0];
    const float* cosT   = (const float*)d_in[1];
    const float* sinT   = (const float*)d_in[2];
    const float* Wq     = (const float*)d_in[3];
    const float* Wk     = (const float*)d_in[4];
    const float* Wv     = (const float*)d_in[5];
    const float* Wo     = (const float*)d_in[6];
    const float* qs     = (const float*)d_in[7];
    const float* ks     = (const float*)d_in[8];
    const float* ls     = (const float*)d_in[9];
    float* out = (float*)d_out;

    cudaFuncSetAttribute(gemm_qkv, cudaFuncAttributeMaxDynamicSharedMemorySize, GEMM_SMEM);
    cudaFuncSetAttribute(gemm_wo,  cudaFuncAttributeMaxDynamicSharedMemorySize, GEMM_SMEM);
    cudaFuncSetAttribute(attn_mma, cudaFuncAttributeMaxDynamicSharedMemorySize, ATT_SMEM);

    // convert activations + all weights to fp16
    conv_act<<<SEQ * HID / 512, 256>>>(hidden);
    conv_wt_all<<<dim3(HID / 32, HID / 32, 4), dim3(32, 8)>>>(Wq, Wk, Wv, Wo);

    // fused QKV projection + RMSNorm + RoPE (Q pre-scaled)
    gemm_qkv<<<dim3(NQKV / 128, SEQ / 128), 256, GEMM_SMEM>>>(cosT, sinT, qs, ks);

    // causal GQA attention (split-K, fixed-offset softmax) + merge/normalize
    attn_mma<<<dim3(NH, 24), 256, ATT_SMEM>>>();
    attn_norm<<<SEQ * HID / 2048, 256>>>();

    // output projection (1-term fp16)
    gemm_wo<<<dim3(HID / 128, SEQ / 128), 256, GEMM_SMEM>>>();

    // final RMSNorm -> d_out
    final_norm_kernel<<<SEQ, 256>>>(ls, out);
}

// round 14
// speedup vs baseline: 2.4845x; 1.0351x over previous
#include <cuda_runtime.h>
#include <cuda_bf16.h>
#include <cuda_fp16.h>
#include <cstdint>
#include <math.h>

#define SEQ 2048
#define HID 2048
#define HD  128
#define NH  16
#define NKV 4
#define KVW (NKV*HD)           // 512
#define NQKV (HID + 2*KVW)     // 3072
#define EPSV 1e-6f
#define BKG 64
#define NSTG 3
#define KCH (HID / BKG)        // 32 k-chunks
#define GP  72                 // gemm smem row stride (halves)

// ---------------- scratch ----------------------------------------------------
__device__ float g_Y[SEQ * HID];

__device__ __half g_Ah[SEQ * HID];               // hidden fp16
__device__ __half g_AOh[SEQ * HID];              // attention-out fp16
__device__ __half g_Wqkv[NQKV * HID];            // W^T fp16
__device__ __half g_Wo[HID * HID];

__device__ __half g_Qf[SEQ * HID];               // Q fp16 (post norm/rope, pre-scaled)
__device__ __half g_Kf[SEQ * KVW];               // K fp16
__device__ __half g_Vf[SEQ * KVW];               // V fp16

// split-K attention partials (rows >= 1024 only are split)
__device__ float g_AOa[SEQ * HID];
__device__ float g_AOb[SEQ * HID];
__device__ float g_La[SEQ * NH];
__device__ float g_Lb[SEQ * NH];

// work-item tables: 24 items/head, descending iteration count
__device__ const int ITEM_QB[24]  = {15,15, 7,14,14,13,13, 6,12,12,11,11, 5,10,10, 4, 9, 9, 8, 8, 3, 2, 1, 0};
__device__ const int ITEM_SPL[24] = { 0, 1, 0, 0, 1, 0, 1, 0, 0, 1, 0, 1, 0, 0, 1, 0, 0, 1, 0, 1, 0, 0, 0, 0};

// ======================= helpers =============================================
__device__ __forceinline__ uint32_t smem_u32(const void* p) {
    uint32_t a;
    asm("{ .reg .u64 t; cvta.to.shared.u64 t, %1; cvt.u32.u64 %0, t; }" : "=r"(a) : "l"(p));
    return a;
}
__device__ __forceinline__ void ldsm4(uint32_t* r, uint32_t addr) {
    asm volatile("ldmatrix.sync.aligned.m8n8.x4.shared.b16 {%0,%1,%2,%3}, [%4];"
        : "=r"(r[0]), "=r"(r[1]), "=r"(r[2]), "=r"(r[3]) : "r"(addr));
}
__device__ __forceinline__ void ldsm4t(uint32_t* r, uint32_t addr) {
    asm volatile("ldmatrix.sync.aligned.m8n8.x4.trans.shared.b16 {%0,%1,%2,%3}, [%4];"
        : "=r"(r[0]), "=r"(r[1]), "=r"(r[2]), "=r"(r[3]) : "r"(addr));
}
__device__ __forceinline__ void mma_f16(float* c, const uint32_t* a, const uint32_t* b) {
    asm volatile(
        "mma.sync.aligned.m16n8k16.row.col.f32.f16.f16.f32 "
        "{%0,%1,%2,%3}, {%4,%5,%6,%7}, {%8,%9}, {%0,%1,%2,%3};"
        : "+f"(c[0]), "+f"(c[1]), "+f"(c[2]), "+f"(c[3])
        : "r"(a[0]), "r"(a[1]), "r"(a[2]), "r"(a[3]), "r"(b[0]), "r"(b[1]));
}
__device__ __forceinline__ void cpa16(void* s, const void* g) {
    uint32_t sa = smem_u32(s);
    asm volatile("cp.async.cg.shared.global [%0], [%1], 16;" :: "r"(sa), "l"(g));
}

// ===== fp16 1-term GEMM core: C = A @ B^T, 3-stage cp.async (2 CTAs/SM) =====
#define STAGE_HALF (2 * 128 * GP)
#define GEMM_SMEM  (NSTG * STAGE_HALF * 2)   // 110,592 B -> 2 CTAs/SM

struct GemmAcc { float a[4][4][4]; };

__device__ __forceinline__ void gemm_core(const __half* __restrict__ A,
                                          const __half* __restrict__ B,
                                          int bm, int bn, __half* gs, GemmAcc& G)
{
    const int tid  = threadIdx.x;
    const int wid  = tid >> 5, lane = tid & 31;
    const int wm   = wid & 1, wn = wid >> 1;
    const uint32_t sbase = smem_u32(gs);

#define ISSUE(c) do {                                                                   \
    int _k0 = (c) * BKG;                                                                \
    __half* _sA = gs + ((c) % NSTG) * STAGE_HALF;                                       \
    __half* _sB = _sA + 128 * GP;                                                       \
    _Pragma("unroll")                                                                   \
    for (int _i = 0; _i < 4; _i++) {                                                    \
        int _id = _i * 256 + tid; int _r = _id >> 3, _u = _id & 7;                      \
        int _so = _r * GP + _u * 8;                                                     \
        cpa16(_sA + _so, A + (size_t)(bm + _r) * HID + _k0 + _u * 8);                   \
        cpa16(_sB + _so, B + (size_t)(bn + _r) * HID + _k0 + _u * 8);                   \
    }                                                                                   \
    asm volatile("cp.async.commit_group;" ::: "memory");                                \
} while (0)

#pragma unroll
    for (int i = 0; i < 4; i++)
#pragma unroll
        for (int j = 0; j < 4; j++)
#pragma unroll
            for (int k = 0; k < 4; k++) G.a[i][j][k] = 0.0f;

    ISSUE(0); ISSUE(1);

    const uint32_t aOff = (uint32_t)((wm * 64 + (lane & 15)) * GP + ((lane >> 4) << 3)) * 2;
    const uint32_t bOff = (uint32_t)((wn * 32 + (lane & 7) + (((lane >> 4) & 1) << 3)) * GP
                                     + (((lane >> 3) & 1) << 3)) * 2;

    for (int c = 0; c < KCH; c++) {
        asm volatile("cp.async.wait_group 1;" ::: "memory");
        __syncthreads();
        if (c + 2 < KCH) { ISSUE(c + 2); }
        else { asm volatile("cp.async.commit_group;" ::: "memory"); }

        const uint32_t aB = sbase + (c % NSTG) * (STAGE_HALF * 2);
        const uint32_t bB = aB + 128 * GP * 2;
#pragma unroll
        for (int ks = 0; ks < 4; ks++) {
            uint32_t ah[4][4], bfr[2][4];
#pragma unroll
            for (int mi = 0; mi < 4; mi++)
                ldsm4(ah[mi], aB + aOff + mi * (16 * GP * 2) + ks * 32);
#pragma unroll
            for (int nj = 0; nj < 2; nj++)
                ldsm4(bfr[nj], bB + bOff + nj * (16 * GP * 2) + ks * 32);
#pragma unroll
            for (int mi = 0; mi < 4; mi++)
#pragma unroll
                for (int ni = 0; ni < 4; ni++)
                    mma_f16(G.a[mi][ni], ah[mi], &bfr[ni >> 1][(ni & 1) * 2]);
        }
    }
#undef ISSUE
}

// ---- fused QKV projection + per-head RMSNorm + RoPE + fp16 outputs ----------
__global__ __launch_bounds__(256) void gemm_qkv(const float* __restrict__ cosT,
                                                const float* __restrict__ sinT,
                                                const float* __restrict__ qscale,
                                                const float* __restrict__ kscale)
{
    extern __shared__ char dynsm[];
    GemmAcc G;
    const int bm = blockIdx.y * 128, bn = blockIdx.x * 128;
    gemm_core(g_Ah, g_Wqkv, bm, bn, (__half*)dynsm, G);

    const int tid = threadIdx.x;
    const int lane = tid & 31, wid = tid >> 5;
    const int wm = wid & 1, wn = wid >> 1;

    asm volatile("cp.async.wait_group 0;" ::: "memory");
    __syncthreads();

    // ---- V tiles ----
    if (bn >= HID + KVW) {
        const int head = (bn - HID - KVW) >> 7;
#pragma unroll
        for (int mi = 0; mi < 4; mi++)
#pragma unroll
            for (int half = 0; half < 2; half++) {
                int s = bm + wm * 64 + mi * 16 + (lane >> 2) + half * 8;
#pragma unroll
                for (int ni = 0; ni < 4; ni++) {
                    int d = wn * 32 + (lane & 3) * 2 + ni * 8;
                    __half2 v = __floats2half2_rn(G.a[mi][ni][half * 2],
                                                  G.a[mi][ni][half * 2 + 1]);
                    *(__half2*)(g_Vf + (size_t)s * KVW + head * HD + d) = v;
                }
            }
        return;
    }

    // ---- Q / K tiles: RMSNorm + RoPE ----
    const bool isQ = (bn < HID);
    const int head = isQ ? (bn >> 7) : ((bn - HID) >> 7);
    const float* sc = isQ ? qscale : kscale;
    const float qmul = isQ ? 0.08838834764831845f : 1.0f;

    float* red = (float*)dynsm;
    float* stg = (float*)dynsm + 512 + 16;
#define STG(r, d) stg[(r) * 132 + (d)]

    float scv[4][2];
#pragma unroll
    for (int ni = 0; ni < 4; ni++) {
#pragma unroll
        for (int e2 = 0; e2 < 2; e2++)
            scv[ni][e2] = sc[wn * 32 + (lane & 3) * 2 + ni * 8 + e2];
    }

#pragma unroll
    for (int mi = 0; mi < 4; mi++) {
#pragma unroll
        for (int half = 0; half < 2; half++) {
            float p = 0.0f;
#pragma unroll
            for (int ni = 0; ni < 4; ni++) {
                float v0 = G.a[mi][ni][half * 2], v1 = G.a[mi][ni][half * 2 + 1];
                p += v0 * v0 + v1 * v1;
            }
            p += __shfl_xor_sync(0xffffffffu, p, 1);
            p += __shfl_xor_sync(0xffffffffu, p, 2);
            if ((lane & 3) == 0) {
                int r = wm * 64 + mi * 16 + (lane >> 2) + half * 8;
                red[r * 4 + wn] = p;
            }
        }
    }
    __syncthreads();

#pragma unroll
    for (int mi = 0; mi < 4; mi++) {
#pragma unroll
        for (int half = 0; half < 2; half++) {
            int r = wm * 64 + mi * 16 + (lane >> 2) + half * 8;
            float tot = red[r * 4] + red[r * 4 + 1] + red[r * 4 + 2] + red[r * 4 + 3];
            float inv = rsqrtf(tot * (1.0f / HD) + EPSV);
#pragma unroll
            for (int ni = 0; ni < 4; ni++) {
#pragma unroll
                for (int e2 = 0; e2 < 2; e2++) {
                    int d = wn * 32 + (lane & 3) * 2 + ni * 8 + e2;
                    float nv = G.a[mi][ni][half * 2 + e2] * inv * scv[ni][e2];
                    G.a[mi][ni][half * 2 + e2] = nv;
                    STG(r, d) = nv;
                }
            }
        }
    }
    __syncthreads();

#pragma unroll
    for (int mi = 0; mi < 4; mi++) {
#pragma unroll
        for (int half = 0; half < 2; half++) {
            int r = wm * 64 + mi * 16 + (lane >> 2) + half * 8;
            int s = bm + r;
#pragma unroll
            for (int ni = 0; ni < 4; ni++) {
                int d = wn * 32 + (lane & 3) * 2 + ni * 8;
                float nv0 = G.a[mi][ni][half * 2], nv1 = G.a[mi][ni][half * 2 + 1];
                float rot0, rot1;
                if (d < 64) { rot0 = -STG(r, d + 64); rot1 = -STG(r, d + 65); }
                else        { rot0 =  STG(r, d - 64); rot1 =  STG(r, d - 63); }
                float2 cv = *(const float2*)(cosT + (size_t)s * HD + d);
                float2 sv = *(const float2*)(sinT + (size_t)s * HD + d);
                float o0 = (nv0 * cv.x + rot0 * sv.x) * qmul;
                float o1 = (nv1 * cv.y + rot1 * sv.y) * qmul;
                __half2 hv = __floats2half2_rn(o0, o1);
                if (isQ) *(__half2*)(g_Qf + (size_t)s * HID + head * HD + d) = hv;
                else     *(__half2*)(g_Kf + (size_t)s * KVW + head * HD + d) = hv;
            }
        }
    }
#undef STG
}

// ---- Wo projection ----
__global__ __launch_bounds__(256) void gemm_wo()
{
    extern __shared__ char dynsm[];
    GemmAcc G;
    const int bm = blockIdx.y * 128, bn = blockIdx.x * 128;
    gemm_core(g_AOh, g_Wo, bm, bn, (__half*)dynsm, G);

    const int lane = threadIdx.x & 31, wid = threadIdx.x >> 5;
    const int cr = bm + (wid & 1) * 64 + (lane >> 2);
    const int cc = bn + (wid >> 1) * 32 + (lane & 3) * 2;
#pragma unroll
    for (int mi = 0; mi < 4; mi++)
#pragma unroll
        for (int ni = 0; ni < 4; ni++) {
            *(float2*)&g_Y[(size_t)(cr + mi * 16) * HID + cc + ni * 8] =
                make_float2(G.a[mi][ni][0], G.a[mi][ni][1]);
            *(float2*)&g_Y[(size_t)(cr + mi * 16 + 8) * HID + cc + ni * 8] =
                make_float2(G.a[mi][ni][2], G.a[mi][ni][3]);
        }
}

// =========== convert hidden: f32 -> fp16 =====================================
__global__ void conv_act(const float* __restrict__ X)
{
    int idx = (blockIdx.x * blockDim.x + threadIdx.x) * 2;
    float2 x = *(const float2*)(X + idx);
    *(__half2*)(g_Ah + idx) = __floats2half2_rn(x.x, x.y);
}

// ==== transpose all 4 weights: W[HID,N] f32 -> Wt[N,HID] fp16, one launch ====
__global__ void conv_wt_all(const float* __restrict__ Wq, const float* __restrict__ Wk,
                            const float* __restrict__ Wv, const float* __restrict__ Wo)
{
    __shared__ float t[32][33];
    const float* W; __half* Wt; int N;
    __half *wqkv = g_Wqkv, *wo = g_Wo;
    switch (blockIdx.z) {
        case 0: W = Wq; Wt = wqkv;                             N = HID; break;
        case 1: W = Wk; Wt = wqkv + (size_t)HID * HID;         N = KVW; break;
        case 2: W = Wv; Wt = wqkv + (size_t)(HID + KVW) * HID; N = KVW; break;
        default: W = Wo; Wt = wo;                              N = HID; break;
    }
    int n0 = blockIdx.x * 32, k0 = blockIdx.y * 32;
    if (n0 >= N) return;
    int tx = threadIdx.x, ty0 = threadIdx.y;
#pragma unroll
    for (int i = 0; i < 4; i++) {
        int ty = ty0 + i * 8;
        t[ty][tx] = W[(size_t)(k0 + ty) * N + n0 + tx];
    }
    __syncthreads();
#pragma unroll
    for (int i = 0; i < 4; i++) {
        int n = n0 + ty0 + i * 8;
        int k = k0 + tx;
        Wt[(size_t)n * HID + k] = __float2half_rn(t[tx][ty0 + i * 8]);
    }
}

// ---------------- causal GQA attention: split-K, fixed-offset softmax --------
// Non-split items (qb<8) normalize + write fp16 AOh directly; split items
// write f32 partials merged by attn_norm (rows >= 1024 only).
#define AP 136
#define KVBUF (2 * 64 * AP)
#define ATT_SMEM ((128 * AP + 2 * KVBUF) * 2)
#define SOFF 4.0f

__global__ __launch_bounds__(256) void attn_mma()
{
    extern __shared__ char dynsm[];
    __half* sm = (__half*)dynsm;
    __half* Qf = sm;
    __half* KV = sm + 128 * AP;

    const int h    = blockIdx.x;
    const int item = blockIdx.y;
    const int qb   = ITEM_QB[item];
    const int spl  = ITEM_SPL[item];
    const bool isSplit = (qb >= 8);
    const int klo = (isSplit && spl == 1) ? (qb + 1) : 0;
    const int khi = (isSplit && spl == 0) ? qb : (2 * qb + 1);

    const int kv = h >> 2;
    const int tid = threadIdx.x, w = tid >> 5, l = tid & 31;

    const __half* gkf = g_Kf + kv * HD;
    const __half* gvf = g_Vf + kv * HD;

#define ISSUE_KV(kb) do {                                                              \
    __half* _d = KV + ((kb) & 1) * KVBUF;                                              \
    size_t _g0 = (size_t)((kb) * 64) * KVW;                                            \
    _Pragma("unroll")                                                                  \
    for (int _i = 0; _i < 4; _i++) {                                                   \
        int _id = _i * 256 + tid; int _r = _id >> 4, _u = _id & 15;                    \
        size_t _go = _g0 + (size_t)_r * KVW + _u * 8;                                  \
        int _so = _r * AP + _u * 8;                                                    \
        cpa16(_d + _so,           gkf + _go);                                          \
        cpa16(_d + 64 * AP + _so, gvf + _go);                                          \
    }                                                                                  \
    asm volatile("cp.async.commit_group;" ::: "memory");                               \
} while (0)

    ISSUE_KV(klo);

    {
        const __half* gq = g_Qf + (size_t)(qb * 128) * HID + h * HD;
#pragma unroll
        for (int i = 0; i < 8; i++) {
            int id = i * 256 + tid;
            int r = id >> 4, u = id & 15;
            *(uint4*)(Qf + r * AP + u * 8) = *(const uint4*)(gq + (size_t)r * HID + u * 8);
        }
    }

    const uint32_t qa = smem_u32(Qf);
    const uint32_t aOff = (uint32_t)((w * 16 + (l & 15)) * AP + ((l >> 4) << 3)) * 2;

    float ls0 = 0.0f, ls1 = 0.0f;
    float accO[16][4];
#pragma unroll
    for (int i = 0; i < 16; i++)
#pragma unroll
        for (int j = 0; j < 4; j++) accO[i][j] = 0.0f;

    for (int kb = klo; kb <= khi; kb++) {
        asm volatile("cp.async.wait_group 0;" ::: "memory");
        __syncthreads();
        if (kb < khi) ISSUE_KV(kb + 1);

        const __half* buf = KV + (kb & 1) * KVBUF;
        const uint32_t ka = smem_u32(buf);
        const uint32_t va = ka + 64 * AP * 2;

        float S[8][4];
#pragma unroll
        for (int t = 0; t < 8; t++)
#pragma unroll
            for (int e = 0; e < 4; e++) S[t][e] = 0.0f;

#pragma unroll
        for (int ks = 0; ks < 8; ks++) {
            uint32_t af[4], bf2[4][4];
            ldsm4(af, qa + aOff + ks * 32);
#pragma unroll
            for (int g = 0; g < 4; g++)
                ldsm4(bf2[g], ka + (uint32_t)((g * 16 + (l & 7) + (((l >> 4) & 1) << 3)) * AP
                                              + (((l >> 3) & 1) << 3)) * 2 + ks * 32);
#pragma unroll
            for (int t = 0; t < 8; t++)
                mma_f16(S[t], af, &bf2[t >> 1][(t & 1) * 2]);
        }

        if (kb >= 2 * qb) {
            int r0 = qb * 128 + w * 16 + (l >> 2), r1 = r0 + 8;
            int cbase = kb * 64 + (l & 3) * 2;
#pragma unroll
            for (int t = 0; t < 8; t++) {
                int cb = cbase + t * 8;
                if (cb     > r0) S[t][0] = -1e30f;
                if (cb + 1 > r0) S[t][1] = -1e30f;
                if (cb     > r1) S[t][2] = -1e30f;
                if (cb + 1 > r1) S[t][3] = -1e30f;
            }
        }

        uint32_t Pa[4][4];
#pragma unroll
        for (int t = 0; t < 8; t++) {
            float p0 = __expf(S[t][0] - SOFF), p1 = __expf(S[t][1] - SOFF);
            float p2 = __expf(S[t][2] - SOFF), p3 = __expf(S[t][3] - SOFF);
            ls0 += p0 + p1; ls1 += p2 + p3;
            __half2 h01 = __floats2half2_rn(p0, p1);
            __half2 h23 = __floats2half2_rn(p2, p3);
            int kc = t >> 1, hi = (t & 1) * 2;
            Pa[kc][hi]     = *(uint32_t*)&h01;
            Pa[kc][hi + 1] = *(uint32_t*)&h23;
        }

#pragma unroll
        for (int kc = 0; kc < 4; kc++) {
            uint32_t vb[8][4];
#pragma unroll
            for (int g = 0; g < 8; g++)
                ldsm4t(vb[g], va + (uint32_t)((kc * 16 + (l & 15)) * AP
                                              + (g * 16 + ((l >> 4) << 3))) * 2);
#pragma unroll
            for (int nd = 0; nd < 16; nd++)
                mma_f16(accO[nd], Pa[kc], &vb[nd >> 1][(nd & 1) * 2]);
        }
    }
#undef ISSUE_KV

    ls0 += __shfl_xor_sync(0xffffffffu, ls0, 1);
    ls0 += __shfl_xor_sync(0xffffffffu, ls0, 2);
    ls1 += __shfl_xor_sync(0xffffffffu, ls1, 1);
    ls1 += __shfl_xor_sync(0xffffffffu, ls1, 2);

    int r0 = qb * 128 + w * 16 + (l >> 2);
    int cc = h * HD + (l & 3) * 2;

    if (!isSplit) {
        // complete row: normalize + write fp16 directly
        float inv0 = 1.0f / ls0, inv1 = 1.0f / ls1;
#pragma unroll
        for (int nd = 0; nd < 16; nd++) {
            __half2 h0 = __floats2half2_rn(accO[nd][0] * inv0, accO[nd][1] * inv0);
            __half2 h1 = __floats2half2_rn(accO[nd][2] * inv1, accO[nd][3] * inv1);
            *(__half2*)(g_AOh + (size_t)r0 * HID + cc + nd * 8)       = h0;
            *(__half2*)(g_AOh + (size_t)(r0 + 8) * HID + cc + nd * 8) = h1;
        }
    } else {
        float* dstA = (spl == 1) ? g_AOb : g_AOa;
        float* dstL = (spl == 1) ? g_Lb  : g_La;
        if ((l & 3) == 0) {
            dstL[(size_t)r0 * NH + h]       = ls0;
            dstL[(size_t)(r0 + 8) * NH + h] = ls1;
        }
#pragma unroll
        for (int nd = 0; nd < 16; nd++) {
            *(float2*)(dstA + (size_t)r0 * HID + cc + nd * 8) =
                make_float2(accO[nd][0], accO[nd][1]);
            *(float2*)(dstA + (size_t)(r0 + 8) * HID + cc + nd * 8) =
                make_float2(accO[nd][2], accO[nd][3]);
        }
    }
}

// ---- merge + normalize split rows (s >= 1024): AOh = (A + B)/(La + Lb) ------
__global__ void attn_norm()
{
    int idx = 1024 * HID + (blockIdx.x * 256 + threadIdx.x) * 8;
    int s = idx >> 11;
    int h = (idx & (HID - 1)) >> 7;

    float lsum = g_La[(size_t)s * NH + h] + g_Lb[(size_t)s * NH + h];
    float inv = 1.0f / lsum;

    float4 a0 = *(float4*)(g_AOa + idx);
    float4 a1 = *(float4*)(g_AOa + idx + 4);
    float4 b0 = *(float4*)(g_AOb + idx);
    float4 b1 = *(float4*)(g_AOb + idx + 4);
    a0.x += b0.x; a0.y += b0.y; a0.z += b0.z; a0.w += b0.w;
    a1.x += b1.x; a1.y += b1.y; a1.z += b1.z; a1.w += b1.w;

    *(__half2*)(g_AOh + idx)     = __floats2half2_rn(a0.x * inv, a0.y * inv);
    *(__half2*)(g_AOh + idx + 2) = __floats2half2_rn(a0.z * inv, a0.w * inv);
    *(__half2*)(g_AOh + idx + 4) = __floats2half2_rn(a1.x * inv, a1.y * inv);
    *(__half2*)(g_AOh + idx + 6) = __floats2half2_rn(a1.z * inv, a1.w * inv);
}

// ---------------- final RMSNorm ----------------------------------------------
__global__ void final_norm_kernel(const float* __restrict__ sc, float* __restrict__ out)
{
    int s = blockIdx.x;
    const float* y = g_Y + (size_t)s * HID;
    float v = 0.0f;
    for (int d = threadIdx.x; d < HID; d += 256) { float x = y[d]; v += x * x; }
#pragma unroll
    for (int m = 16; m > 0; m >>= 1) v += __shfl_xor_sync(0xffffffffu, v, m);
    __shared__ float ws[8];
    if ((threadIdx.x & 31) == 0) ws[threadIdx.x >> 5] = v;
    __syncthreads();
    float tot = 0.0f;
#pragma unroll
    for (int i = 0; i < 8; i++) tot += ws[i];
    float inv = rsqrtf(tot * (1.0f / HID) + EPSV);
    for (int d = threadIdx.x; d < HID; d += 256)
        out[(size_t)s * HID + d] = y[d] * inv * sc[d];
}

// ---------------- launch -----------------------------------------------------
extern "C" void kernel_launch(void* const* d_in, const int* in_sizes, int n_in,
                              void* d_out, int out_size)
{
    const float* hidden = (const float*)d_in[0];
    const float* cosT   = (const float*)d_in[1];
    const float* sinT   = (const float*)d_in[2];
    const float* Wq     = (const float*)d_in[3];
    const float* Wk     = (const float*)d_in[4];
    const float* Wv     = (const float*)d_in[5];
    const float* Wo     = (const float*)d_in[6];
    const float* qs     = (const float*)d_in[7];
    const float* ks     = (const float*)d_in[8];
    const float* ls     = (const float*)d_in[9];
    float* out = (float*)d_out;

    cudaFuncSetAttribute(gemm_qkv, cudaFuncAttributeMaxDynamicSharedMemorySize, GEMM_SMEM);
    cudaFuncSetAttribute(gemm_wo,  cudaFuncAttributeMaxDynamicSharedMemorySize, GEMM_SMEM);
    cudaFuncSetAttribute(attn_mma, cudaFuncAttributeMaxDynamicSharedMemorySize, ATT_SMEM);

    // convert activations + all weights to fp16
    conv_act<<<SEQ * HID / 512, 256>>>(hidden);
    conv_wt_all<<<dim3(HID / 32, HID / 32, 4), dim3(32, 8)>>>(Wq, Wk, Wv, Wo);

    // fused QKV projection + RMSNorm + RoPE (Q pre-scaled); 2 CTAs/SM
    gemm_qkv<<<dim3(NQKV / 128, SEQ / 128), 256, GEMM_SMEM>>>(cosT, sinT, qs, ks);

    // causal GQA attention (split-K) + merge for split rows only
    attn_mma<<<dim3(NH, 24), 256, ATT_SMEM>>>();
    attn_norm<<<SEQ * HID / 4096, 256>>>();

    // output projection; 2 CTAs/SM
    gemm_wo<<<dim3(HID / 128, SEQ / 128), 256, GEMM_SMEM>>>();

    // final RMSNorm -> d_out
    final_norm_kernel<<<SEQ, 256>>>(ls, out);
}